// round 13
// baseline (speedup 1.0000x reference)
#include <cuda_runtime.h>
#include <cuda_bf16.h>
#include <cuda_fp16.h>
#include <cstdint>
#include <math.h>

#define NROWS 32768
#define FDIM  128
#define KDIM  64
#define MNBR  32
#define NTILES (NROWS/4)

// Scratch (allocation-free rule: __device__ globals)
__device__ float g_xi [NROWS*FDIM];
__device__ float g_m0 [NROWS*FDIM];
__device__ float g_m1 [NROWS*FDIM];
__device__ __align__(16) __half g_xjpH[NROWS*FDIM];  // xjp in fp16 (gather table)
__device__ __align__(16) __half g_wfH[7*16384];
__device__ __align__(16) __half g_wfL[7*16384];
__device__ __align__(16) __half g_tf[NROWS*FDIM];    // raw t (fp16)
__device__ __align__(16) __half g_sf[NROWS*FDIM];    // ssp-activation (fp16)

__device__ __forceinline__ float sspf(float a) {
    return fmaxf(a, 0.0f) + log1pf(expf(-fabsf(a))) - 0.69314718055994530942f;
}

// ---------------- mma.sync / cp.async helpers ----------------
__device__ __forceinline__ uint32_t s2u(const void* p) {
    uint32_t a;
    asm("{ .reg .u64 t; cvta.to.shared.u64 t, %1; cvt.u32.u64 %0, t; }" : "=r"(a) : "l"(p));
    return a;
}

#define LDM_X4(r, addr) \
    asm volatile("ldmatrix.sync.aligned.m8n8.x4.shared.b16 {%0,%1,%2,%3}, [%4];" \
        : "=r"((r)[0]), "=r"((r)[1]), "=r"((r)[2]), "=r"((r)[3]) : "r"(addr))

#define MMA_F16(d, a, b0, b1) \
    asm volatile("mma.sync.aligned.m16n8k16.row.col.f32.f16.f16.f32 " \
        "{%0,%1,%2,%3}, {%4,%5,%6,%7}, {%8,%9}, {%0,%1,%2,%3};" \
        : "+f"((d)[0]), "+f"((d)[1]), "+f"((d)[2]), "+f"((d)[3]) \
        : "r"((a)[0]), "r"((a)[1]), "r"((a)[2]), "r"((a)[3]), "r"(b0), "r"(b1))

#define CP16(dst, src) \
    asm volatile("cp.async.cg.shared.global [%0], [%1], 16;" :: "r"(dst), "l"(src) : "memory")
#define CP_COMMIT() asm volatile("cp.async.commit_group;" ::: "memory")
#define CP_WAIT0()  asm volatile("cp.async.wait_group 0;" ::: "memory")

__device__ __forceinline__ void f16_split4(float4 v, __half* H, __half* L) {
    __half h0 = __float2half_rn(v.x), h1 = __float2half_rn(v.y),
           h2 = __float2half_rn(v.z), h3 = __float2half_rn(v.w);
    *(__half2*)(H)     = __half2(h0, h1);
    *(__half2*)(H + 2) = __half2(h2, h3);
    *(__half2*)(L)     = __half2(__float2half_rn(v.x - __half2float(h0)),
                                 __float2half_rn(v.y - __half2float(h1)));
    *(__half2*)(L + 2) = __half2(__float2half_rn(v.z - __half2float(h2)),
                                 __float2half_rn(v.w - __half2float(h3)));
}

// ---------------- weight pre-split: 7 matrices of 128x128 (fp16 hi/lo, exact) ----------------
__global__ void __launch_bounds__(256) prep_w(
    const float* __restrict__ wi, const float* __restrict__ wj,
    const float* __restrict__ rw1, const float* __restrict__ rw2,
    const float* __restrict__ wd,
    __half* __restrict__ WH, __half* __restrict__ WL)
{
    int idx = blockIdx.x * 256 + threadIdx.x;
    int mat = idx >> 12, off = idx & 4095;
    const float* src;
    switch (mat) {
        case 0: src = wi; break;
        case 1: src = wj; break;
        case 2: src = rw1; break;
        case 3: src = rw2; break;
        case 4: src = rw1 + 16384; break;
        case 5: src = rw2 + 16384; break;
        default: src = wd; break;
    }
    float4 v = ((const float4*)src)[off];
    size_t d = (size_t)mat * 16384 + (size_t)off * 4;
    f16_split4(v, WH + d, WL + d);
}

// =================================================================================
// Tensor-core row GEMM: fp16 2-pass (W = hi/lo exact, A = single fp16).
// 256 threads, 64x128 tile, 2 CTAs/SM.  (validated R11/R12)
// =================================================================================
#define TG_WH    0u
#define TG_WL    34816u
#define TG_U     69632u
#define TG_AH    TG_U
#define TG_BIAS  103424u
#define TG_MUL   103936u
#define TG_TOTAL 104448u
#define TG_SLABS 132

template<int AMODE, bool ADD, bool MULVEC, bool OUTF32, bool OUTSPLIT, bool OSSP>
__global__ __launch_bounds__(256, 2) void tg2(
    const void* __restrict__ aSrc,
    const __half* __restrict__ wHsrc, const __half* __restrict__ wLsrc,
    const float* __restrict__ bias, const float* __restrict__ addp,
    const float* __restrict__ mulv, float* __restrict__ outf,
    __half* __restrict__ oH)
{
    extern __shared__ char smem[];
    __half* AH = (__half*)(smem + TG_AH);
    float* slab = (float*)(smem + TG_U);
    float* b_sm = (float*)(smem + TG_BIAS);
    float* u_sm = (float*)(smem + TG_MUL);

    const int tid = threadIdx.x;
    const int wid = tid >> 5, lid = tid & 31;
    const uint32_t sb = s2u(smem);

    #pragma unroll
    for (int i = 0; i < 8; i++) {
        int idx = tid + 256 * i;
        int row = idx >> 4, c8 = idx & 15;
        *(uint4*)(smem + TG_WH + row * 272 + c8 * 16) = ((const uint4*)wHsrc)[idx];
        *(uint4*)(smem + TG_WL + row * 272 + c8 * 16) = ((const uint4*)wLsrc)[idx];
    }
    if (tid < 128) {
        b_sm[tid] = bias[tid];
        u_sm[tid] = MULVEC ? mulv[tid] : 0.0f;
    }

    const int r0 = blockIdx.x * 64;

    if (AMODE == 0) {
        #pragma unroll
        for (int i = 0; i < 8; i++) {
            int fidx = tid + 256 * i;
            float4 v = ((const float4*)((const float*)aSrc + (size_t)r0 * FDIM))[fidx];
            v.x = sspf(v.x); v.y = sspf(v.y); v.z = sspf(v.z); v.w = sspf(v.w);
            int row = fidx >> 5, c = (fidx & 31) * 4;
            __half* dst = AH + row * 136 + c;
            *(__half2*)(dst)     = __floats2half2_rn(v.x, v.y);
            *(__half2*)(dst + 2) = __floats2half2_rn(v.z, v.w);
        }
    } else {
        const uint4* a4 = (const uint4*)((const __half*)aSrc + (size_t)r0 * FDIM);
        #pragma unroll
        for (int i = 0; i < 4; i++) {
            int idx = tid + 256 * i;
            int row = idx >> 4, c8 = idx & 15;
            *(uint4*)(smem + TG_AH + row * 272 + c8 * 16) = a4[idx];
        }
    }
    __syncthreads();

    const uint32_t aL_off = (((lid & 7) + (lid & 8)) * 136 + ((lid & 16) ? 8 : 0)) * 2;
    const uint32_t bL_off = (((lid & 7) + ((lid & 16) >> 1)) * 136 + ((lid & 8) ? 8 : 0)) * 2;
    const int wr = wid & 1, wc = wid >> 1;

    float acc[2][4][4];
    #pragma unroll
    for (int mt = 0; mt < 2; mt++)
        #pragma unroll
        for (int nb = 0; nb < 4; nb++)
            #pragma unroll
            for (int c = 0; c < 4; c++) acc[mt][nb][c] = 0.f;

    #pragma unroll
    for (int kk = 0; kk < 8; kk++) {
        const uint32_t kb = (uint32_t)kk * 32;
        uint32_t ah[2][4], bh[2][4], bl[2][4];
        #pragma unroll
        for (int mt = 0; mt < 2; mt++) {
            uint32_t ro = (uint32_t)(32*wr + 16*mt) * 272 + kb;
            LDM_X4(ah[mt], sb + TG_AH + aL_off + ro);
        }
        #pragma unroll
        for (int np = 0; np < 2; np++) {
            uint32_t no = (uint32_t)(32*wc + 16*np) * 272 + kb;
            LDM_X4(bh[np], sb + TG_WH + bL_off + no);
            LDM_X4(bl[np], sb + TG_WL + bL_off + no);
        }
        #pragma unroll
        for (int mt = 0; mt < 2; mt++)
            #pragma unroll
            for (int np = 0; np < 2; np++) {
                MMA_F16(acc[mt][2*np],   ah[mt], bh[np][0], bh[np][1]);
                MMA_F16(acc[mt][2*np+1], ah[mt], bh[np][2], bh[np][3]);
                MMA_F16(acc[mt][2*np],   ah[mt], bl[np][0], bl[np][1]);
                MMA_F16(acc[mt][2*np+1], ah[mt], bl[np][2], bl[np][3]);
            }
    }
    __syncthreads();

    {
        const int g = lid >> 2, t = lid & 3;
        #pragma unroll
        for (int mt = 0; mt < 2; mt++)
            #pragma unroll
            for (int nb = 0; nb < 4; nb++) {
                int e = 32*wr + 16*mt + g;
                int c = 32*wc + 8*nb + 2*t;
                *(float2*)&slab[e * TG_SLABS + c] = make_float2(acc[mt][nb][0], acc[mt][nb][1]);
                *(float2*)&slab[(e+8) * TG_SLABS + c] = make_float2(acc[mt][nb][2], acc[mt][nb][3]);
            }
    }
    __syncthreads();

    #pragma unroll
    for (int i = 0; i < 32; i++) {
        int idx = tid + 256 * i;
        int row = idx >> 7, col = idx & 127;
        size_t gpos = (size_t)(r0 + row) * FDIM + col;
        float o = slab[row * TG_SLABS + col] + b_sm[col];
        if (ADD) {
            float av = addp[gpos];
            o += MULVEC ? av * u_sm[col] : av;
        }
        if (OUTF32) outf[gpos] = o;
        if (OUTSPLIT) {
            float s = OSSP ? sspf(o) : o;
            oH[gpos] = __float2half_rn(s);
        }
    }
}

// =================================================================================
// Fused edge-filter GEMM + gather + attention — fp16 single-B MMA, no staging,
// 97.5 KB smem -> 2 CTAs/SM (peer CTA hides LDG + phase latency).
// =================================================================================
#define OFF_BH   0u              // 18432
#define OFF_U    18432u          // AH fp16 128x72x2=18432 | slab fp16 128x136x2=34816
#define OFF_AH   OFF_U
#define OFF_XPB  53248u          // gathered xjp fp16 [128][128] = 32768
#define OFF_XI2  86016u          // 2 x 2048 (double-buffered xi, fp32)
#define OFF_PART 90112u          // float[2048]
#define OFF_ATT  98304u          // float[128]
#define OFF_JB   98816u          // 2 x 512 (double-buffered jidx)
#define SM_TOTAL 99840u
#define SLAB_H   136             // halves per slab row

__global__ void __launch_bounds__(512, 2) attn_mma(
    const float* __restrict__ rbf, const int* __restrict__ idxj,
    const float* __restrict__ k2f, const float* __restrict__ xi,
    const __half* __restrict__ xjph, float* __restrict__ mout,
    __half* __restrict__ oH)
{
    extern __shared__ char smem[];
    __half* AH = (__half*)(smem + OFF_AH);
    __half* BH = (__half*)(smem + OFF_BH);
    __half* slabh = (__half*)(smem + OFF_U);
    __half* xpbh  = (__half*)(smem + OFF_XPB);
    float* part   = (float*)(smem + OFF_PART);
    float* att_sm = (float*)(smem + OFF_ATT);

    const int tid = threadIdx.x;
    const int wid = tid >> 5, lid = tid & 31;
    const uint32_t sb = s2u(smem);

    // B = k2f, single fp16, once
    #pragma unroll
    for (int i = 0; i < 4; i++) {
        int fidx = tid + 512 * i;
        float4 v = ((const float4*)k2f)[fidx];
        int row = fidx >> 4, c = (fidx & 15) * 4;
        __half* dst = BH + row*72 + c;
        *(__half2*)(dst)     = __floats2half2_rn(v.x, v.y);
        *(__half2*)(dst + 2) = __floats2half2_rn(v.z, v.w);
    }

    const uint32_t aL = ((((lid & 7) + (lid & 8)) * 72) + ((lid & 16) ? 8 : 0)) * 2;
    const uint32_t bL = ((((lid & 7) + ((lid & 16) >> 1)) * 72) + ((lid & 8) ? 8 : 0)) * 2;
    const int wr = wid & 3, wc = wid >> 2;
    const int f  = tid & 127;
    const int q  = f >> 5;
    const int e0 = tid >> 7;
    const int stride = gridDim.x;

    auto stage = [&](int tile, int sel) {
        if (tid < 128)
            CP16(sb + OFF_XI2 + (uint32_t)sel * 2048u + tid * 16u,
                 (const char*)(xi + (size_t)tile * 512) + tid * 16);
        if (tid < 32)
            CP16(sb + OFF_JB + (uint32_t)sel * 512u + tid * 16u,
                 (const char*)(idxj + tile * 128) + tid * 16);
    };
    // gather fp16 rows: each row = 256 B = 16 lanes x 16 B; 2 rows per warp-step
    auto gather = [&](int sel) {
        const int* jb = (const int*)(smem + OFF_JB + sel * 512);
        const int half_sel = lid >> 4;
        const uint32_t lane_off = (uint32_t)(lid & 15) * 16u;
        #pragma unroll
        for (int r = 0; r < 4; r++) {
            int e = wid * 8 + r * 2 + half_sel;
            int j = jb[e];
            CP16(sb + OFF_XPB + (uint32_t)e * 256u + lane_off,
                 (const char*)(xjph + (size_t)j * FDIM) + lane_off);
        }
    };

    int cur = 0;
    stage(blockIdx.x, 0);
    CP_COMMIT();
    CP_WAIT0();
    __syncthreads();
    gather(0);
    CP_COMMIT();

    for (int tile = blockIdx.x; tile < NTILES; tile += stride) {
        const int n0 = tile * 4;
        const int nxt = tile + stride;
        const bool has = nxt < NTILES;

        // A: direct LDG fp32 -> single fp16 (peer CTA hides the latency)
        {
            const float4* rp = (const float4*)(rbf + (size_t)tile * 8192);
            float4 va[4];
            #pragma unroll
            for (int i = 0; i < 4; i++) va[i] = rp[tid + 512 * i];
            #pragma unroll
            for (int i = 0; i < 4; i++) {
                int fidx = tid + 512 * i;
                int row = fidx >> 4, c = (fidx & 15) * 4;
                __half* dst = AH + row*72 + c;
                *(__half2*)(dst)     = __floats2half2_rn(va[i].x, va[i].y);
                *(__half2*)(dst + 2) = __floats2half2_rn(va[i].z, va[i].w);
            }
        }
        if (has) stage(nxt, cur ^ 1);
        CP_COMMIT();
        __syncthreads();

        // MMA 128x128x64: D = A*B, single fp16 pass
        float acc[2][4][4];
        #pragma unroll
        for (int mt = 0; mt < 2; mt++)
            #pragma unroll
            for (int nb = 0; nb < 4; nb++)
                #pragma unroll
                for (int c = 0; c < 4; c++) acc[mt][nb][c] = 0.f;

        #pragma unroll
        for (int kk = 0; kk < 4; kk++) {
            const uint32_t kb = (uint32_t)kk * 32;
            uint32_t ah[2][4], bh[2][4];
            #pragma unroll
            for (int mt = 0; mt < 2; mt++) {
                uint32_t ro = (uint32_t)(32*wr + 16*mt) * 144 + kb;
                LDM_X4(ah[mt], sb + OFF_AH + aL + ro);
            }
            #pragma unroll
            for (int np = 0; np < 2; np++) {
                uint32_t no = (uint32_t)(32*wc + 16*np) * 144 + kb;
                LDM_X4(bh[np], sb + OFF_BH + bL + no);
            }
            #pragma unroll
            for (int mt = 0; mt < 2; mt++)
                #pragma unroll
                for (int np = 0; np < 2; np++) {
                    MMA_F16(acc[mt][2*np],   ah[mt], bh[np][0], bh[np][1]);
                    MMA_F16(acc[mt][2*np+1], ah[mt], bh[np][2], bh[np][3]);
                }
        }
        __syncthreads();   // A dead -> fp16 slab

        {
            const int g = lid >> 2, t = lid & 3;
            #pragma unroll
            for (int mt = 0; mt < 2; mt++)
                #pragma unroll
                for (int nb = 0; nb < 4; nb++) {
                    int e = 32*wr + 16*mt + g;
                    int c = 32*wc + 8*nb + 2*t;
                    *(__half2*)&slabh[e * SLAB_H + c] =
                        __floats2half2_rn(acc[mt][nb][0], acc[mt][nb][1]);
                    *(__half2*)&slabh[(e + 8) * SLAB_H + c] =
                        __floats2half2_rn(acc[mt][nb][2], acc[mt][nb][3]);
                }
        }
        CP_WAIT0();
        __syncthreads();

        const float* xi_c = (const float*)(smem + OFF_XI2 + (uint32_t)cur * 2048u);

        float xp[32];
        float lacc[4] = {0.f, 0.f, 0.f, 0.f};
        #pragma unroll
        for (int i = 0; i < 32; i++) {
            const int e = 4*i + e0;
            const int a = i >> 3;
            const int m = e & 31;
            float p = __half2float(slabh[e * SLAB_H + f]) * __half2float(xpbh[e * 128 + f]);
            xp[i] = p;
            lacc[a] += xi_c[a * FDIM + 4*m + q] * p;
        }
        #pragma unroll
        for (int a = 0; a < 4; a++)
            part[wid * 128 + a * 32 + lid] = lacc[a];
        __syncthreads();

        if (wid < 4) {
            float lg = 0.f;
            #pragma unroll
            for (int w2 = 0; w2 < 16; w2++) lg += part[w2 * 128 + wid * 32 + lid];
            float mx = lg;
            #pragma unroll
            for (int o = 16; o; o >>= 1) mx = fmaxf(mx, __shfl_xor_sync(0xffffffffu, mx, o));
            float ex = expf(lg - mx);
            float smv = ex;
            #pragma unroll
            for (int o = 16; o; o >>= 1) smv += __shfl_xor_sync(0xffffffffu, smv, o);
            att_sm[wid * 32 + lid] = ex / smv;
        }
        __syncthreads();

        float pacc[4] = {0.f, 0.f, 0.f, 0.f};
        #pragma unroll
        for (int i = 0; i < 32; i++) {
            const int e = 4*i + e0;
            const int a = i >> 3;
            const int m = e & 31;
            pacc[a] += att_sm[a * 32 + m] * xp[i];
        }
        #pragma unroll
        for (int a = 0; a < 4; a++)
            part[e0 * 512 + a * 128 + f] = pacc[a];
        __syncthreads();

        {
            size_t gpos = (size_t)n0 * FDIM + tid;
            float mv = xi_c[tid]
                + part[tid] + part[512 + tid] + part[1024 + tid] + part[1536 + tid];
            mout[gpos] = mv;
            oH[gpos] = __float2half_rn(sspf(mv));
        }

        if (has) gather(cur ^ 1);
        CP_COMMIT();
        __syncthreads();
        cur ^= 1;
    }
}

extern "C" void kernel_launch(void* const* d_in, const int* in_sizes, int n_in,
                              void* d_out, int out_size)
{
    const float* x    = (const float*)d_in[0];
    const float* rbf  = (const float*)d_in[1];
    const int*   idxj = (const int*)  d_in[3];
    const float* k2f  = (const float*)d_in[4];
    const float* wi   = (const float*)d_in[5];
    const float* bi   = (const float*)d_in[6];
    const float* wj   = (const float*)d_in[7];
    const float* bj   = (const float*)d_in[8];
    const float* rw1  = (const float*)d_in[9];
    const float* rb1  = (const float*)d_in[10];
    const float* rw2  = (const float*)d_in[11];
    const float* rb2  = (const float*)d_in[12];
    const float* wd   = (const float*)d_in[13];
    const float* bd   = (const float*)d_in[14];
    const float* u    = (const float*)d_in[15];
    float* out = (float*)d_out;

    float *xi_p, *m0_p, *m1_p;
    __half *xjpH, *wfH, *wfL, *tf, *sf;
    cudaGetSymbolAddress((void**)&xi_p,  g_xi);
    cudaGetSymbolAddress((void**)&m0_p,  g_m0);
    cudaGetSymbolAddress((void**)&m1_p,  g_m1);
    cudaGetSymbolAddress((void**)&xjpH,  g_xjpH);
    cudaGetSymbolAddress((void**)&wfH,   g_wfH);
    cudaGetSymbolAddress((void**)&wfL,   g_wfL);
    cudaGetSymbolAddress((void**)&tf,    g_tf);
    cudaGetSymbolAddress((void**)&sf,    g_sf);

    static int nsm = 0;
    if (nsm == 0) {
        cudaDeviceGetAttribute(&nsm, cudaDevAttrMultiProcessorCount, 0);
        if (nsm <= 0) nsm = 148;
        cudaFuncSetAttribute(attn_mma, cudaFuncAttributeMaxDynamicSharedMemorySize, SM_TOTAL);
        cudaFuncSetAttribute(tg2<0,false,false,true,false,false>,  cudaFuncAttributeMaxDynamicSharedMemorySize, TG_TOTAL);
        cudaFuncSetAttribute(tg2<0,false,false,false,true,false>,  cudaFuncAttributeMaxDynamicSharedMemorySize, TG_TOTAL);
        cudaFuncSetAttribute(tg2<1,false,false,false,true,false>,  cudaFuncAttributeMaxDynamicSharedMemorySize, TG_TOTAL);
        cudaFuncSetAttribute(tg2<1,true,false,true,true,true>,     cudaFuncAttributeMaxDynamicSharedMemorySize, TG_TOTAL);
        cudaFuncSetAttribute(tg2<1,true,false,false,true,true>,    cudaFuncAttributeMaxDynamicSharedMemorySize, TG_TOTAL);
        cudaFuncSetAttribute(tg2<1,true,true,true,false,false>,    cudaFuncAttributeMaxDynamicSharedMemorySize, TG_TOTAL);
    }

    const int TG_GRID = NROWS / 64;   // 512

    prep_w<<<112, 256>>>(wi, wj, rw1, rw2, wd, wfH, wfL);

    // xi = ssp(x)@wi.T+bi (fp32) ; xjp = ssp(x)@wj.T+bj (fp16 gather table)
    tg2<0,false,false,true,false,false><<<TG_GRID, 256, TG_TOTAL>>>(
        x, wfH, wfL, bi, nullptr, nullptr, xi_p, nullptr);
    tg2<0,false,false,false,true,false><<<TG_GRID, 256, TG_TOTAL>>>(
        x, wfH + 16384, wfL + 16384, bj, nullptr, nullptr, nullptr, xjpH);

    // m0 = attention; emits fp16 ssp(m0) -> sf
    attn_mma<<<2 * nsm, 512, SM_TOTAL>>>(rbf, idxj, k2f, xi_p, xjpH, m0_p, sf);

    // res block 0
    tg2<1,false,false,false,true,false><<<TG_GRID, 256, TG_TOTAL>>>(
        sf, wfH + 2*16384, wfL + 2*16384, rb1, nullptr, nullptr, nullptr, tf);
    tg2<1,true,false,true,true,true><<<TG_GRID, 256, TG_TOTAL>>>(
        tf, wfH + 3*16384, wfL + 3*16384, rb2, m0_p, nullptr, m1_p, sf);

    // res block 1
    tg2<1,false,false,false,true,false><<<TG_GRID, 256, TG_TOTAL>>>(
        sf, wfH + 4*16384, wfL + 4*16384, rb1 + FDIM, nullptr, nullptr, nullptr, tf);
    tg2<1,true,false,false,true,true><<<TG_GRID, 256, TG_TOTAL>>>(
        tf, wfH + 5*16384, wfL + 5*16384, rb2 + FDIM, m1_p, nullptr, nullptr, sf);

    // out = u*x + ssp(m2)@wd+bd
    tg2<1,true,true,true,false,false><<<TG_GRID, 256, TG_TOTAL>>>(
        sf, wfH + 6*16384, wfL + 6*16384, bd, x, u, out, nullptr);
}

// round 14
// speedup vs baseline: 1.4962x; 1.4962x over previous
#include <cuda_runtime.h>
#include <cuda_bf16.h>
#include <cuda_fp16.h>
#include <cstdint>
#include <math.h>

#define NROWS 32768
#define FDIM  128
#define KDIM  64
#define MNBR  32
#define NTILES (NROWS/4)

// Scratch (allocation-free rule: __device__ globals)
__device__ float g_xi [NROWS*FDIM];
__device__ float g_m0 [NROWS*FDIM];
__device__ float g_m1 [NROWS*FDIM];
__device__ __align__(16) __half g_xjpH[NROWS*FDIM];  // xjp in fp16 (gather table)
__device__ __align__(16) __half g_wfH[7*16384];
__device__ __align__(16) __half g_wfL[7*16384];
__device__ __align__(16) __half g_tf[NROWS*FDIM];    // raw t (fp16)
__device__ __align__(16) __half g_sf[NROWS*FDIM];    // ssp-activation (fp16)

__device__ __forceinline__ float sspf(float a) {
    return fmaxf(a, 0.0f) + log1pf(expf(-fabsf(a))) - 0.69314718055994530942f;
}

// ---------------- mma.sync / cp.async helpers ----------------
__device__ __forceinline__ uint32_t s2u(const void* p) {
    uint32_t a;
    asm("{ .reg .u64 t; cvta.to.shared.u64 t, %1; cvt.u32.u64 %0, t; }" : "=r"(a) : "l"(p));
    return a;
}

#define LDM_X4(r, addr) \
    asm volatile("ldmatrix.sync.aligned.m8n8.x4.shared.b16 {%0,%1,%2,%3}, [%4];" \
        : "=r"((r)[0]), "=r"((r)[1]), "=r"((r)[2]), "=r"((r)[3]) : "r"(addr))

#define MMA_F16(d, a, b0, b1) \
    asm volatile("mma.sync.aligned.m16n8k16.row.col.f32.f16.f16.f32 " \
        "{%0,%1,%2,%3}, {%4,%5,%6,%7}, {%8,%9}, {%0,%1,%2,%3};" \
        : "+f"((d)[0]), "+f"((d)[1]), "+f"((d)[2]), "+f"((d)[3]) \
        : "r"((a)[0]), "r"((a)[1]), "r"((a)[2]), "r"((a)[3]), "r"(b0), "r"(b1))

#define CP16(dst, src) \
    asm volatile("cp.async.cg.shared.global [%0], [%1], 16;" :: "r"(dst), "l"(src) : "memory")
#define CP_COMMIT() asm volatile("cp.async.commit_group;" ::: "memory")
#define CP_WAIT0()  asm volatile("cp.async.wait_group 0;" ::: "memory")

__device__ __forceinline__ void f16_split4(float4 v, __half* H, __half* L) {
    __half h0 = __float2half_rn(v.x), h1 = __float2half_rn(v.y),
           h2 = __float2half_rn(v.z), h3 = __float2half_rn(v.w);
    *(__half2*)(H)     = __half2(h0, h1);
    *(__half2*)(H + 2) = __half2(h2, h3);
    *(__half2*)(L)     = __half2(__float2half_rn(v.x - __half2float(h0)),
                                 __float2half_rn(v.y - __half2float(h1)));
    *(__half2*)(L + 2) = __half2(__float2half_rn(v.z - __half2float(h2)),
                                 __float2half_rn(v.w - __half2float(h3)));
}

// ---------------- weight pre-split: 7 matrices of 128x128 (fp16 hi/lo, exact) ----------------
__global__ void __launch_bounds__(256) prep_w(
    const float* __restrict__ wi, const float* __restrict__ wj,
    const float* __restrict__ rw1, const float* __restrict__ rw2,
    const float* __restrict__ wd,
    __half* __restrict__ WH, __half* __restrict__ WL)
{
    int idx = blockIdx.x * 256 + threadIdx.x;
    int mat = idx >> 12, off = idx & 4095;
    const float* src;
    switch (mat) {
        case 0: src = wi; break;
        case 1: src = wj; break;
        case 2: src = rw1; break;
        case 3: src = rw2; break;
        case 4: src = rw1 + 16384; break;
        case 5: src = rw2 + 16384; break;
        default: src = wd; break;
    }
    float4 v = ((const float4*)src)[off];
    size_t d = (size_t)mat * 16384 + (size_t)off * 4;
    f16_split4(v, WH + d, WL + d);
}

// =================================================================================
// Tensor-core row GEMM: fp16 2-pass (W = hi/lo exact, A = single fp16).
// 256 threads, 64x128 tile, 2 CTAs/SM.  (validated R11/R12)
// =================================================================================
#define TG_WH    0u
#define TG_WL    34816u
#define TG_U     69632u
#define TG_AH    TG_U
#define TG_BIAS  103424u
#define TG_MUL   103936u
#define TG_TOTAL 104448u
#define TG_SLABS 132

template<int AMODE, bool ADD, bool MULVEC, bool OUTF32, bool OUTSPLIT, bool OSSP>
__global__ __launch_bounds__(256, 2) void tg2(
    const void* __restrict__ aSrc,
    const __half* __restrict__ wHsrc, const __half* __restrict__ wLsrc,
    const float* __restrict__ bias, const float* __restrict__ addp,
    const float* __restrict__ mulv, float* __restrict__ outf,
    __half* __restrict__ oH)
{
    extern __shared__ char smem[];
    __half* AH = (__half*)(smem + TG_AH);
    float* slab = (float*)(smem + TG_U);
    float* b_sm = (float*)(smem + TG_BIAS);
    float* u_sm = (float*)(smem + TG_MUL);

    const int tid = threadIdx.x;
    const int wid = tid >> 5, lid = tid & 31;
    const uint32_t sb = s2u(smem);

    #pragma unroll
    for (int i = 0; i < 8; i++) {
        int idx = tid + 256 * i;
        int row = idx >> 4, c8 = idx & 15;
        *(uint4*)(smem + TG_WH + row * 272 + c8 * 16) = ((const uint4*)wHsrc)[idx];
        *(uint4*)(smem + TG_WL + row * 272 + c8 * 16) = ((const uint4*)wLsrc)[idx];
    }
    if (tid < 128) {
        b_sm[tid] = bias[tid];
        u_sm[tid] = MULVEC ? mulv[tid] : 0.0f;
    }

    const int r0 = blockIdx.x * 64;

    if (AMODE == 0) {
        #pragma unroll
        for (int i = 0; i < 8; i++) {
            int fidx = tid + 256 * i;
            float4 v = ((const float4*)((const float*)aSrc + (size_t)r0 * FDIM))[fidx];
            v.x = sspf(v.x); v.y = sspf(v.y); v.z = sspf(v.z); v.w = sspf(v.w);
            int row = fidx >> 5, c = (fidx & 31) * 4;
            __half* dst = AH + row * 136 + c;
            *(__half2*)(dst)     = __floats2half2_rn(v.x, v.y);
            *(__half2*)(dst + 2) = __floats2half2_rn(v.z, v.w);
        }
    } else {
        const uint4* a4 = (const uint4*)((const __half*)aSrc + (size_t)r0 * FDIM);
        #pragma unroll
        for (int i = 0; i < 4; i++) {
            int idx = tid + 256 * i;
            int row = idx >> 4, c8 = idx & 15;
            *(uint4*)(smem + TG_AH + row * 272 + c8 * 16) = a4[idx];
        }
    }
    __syncthreads();

    const uint32_t aL_off = (((lid & 7) + (lid & 8)) * 136 + ((lid & 16) ? 8 : 0)) * 2;
    const uint32_t bL_off = (((lid & 7) + ((lid & 16) >> 1)) * 136 + ((lid & 8) ? 8 : 0)) * 2;
    const int wr = wid & 1, wc = wid >> 1;

    float acc[2][4][4];
    #pragma unroll
    for (int mt = 0; mt < 2; mt++)
        #pragma unroll
        for (int nb = 0; nb < 4; nb++)
            #pragma unroll
            for (int c = 0; c < 4; c++) acc[mt][nb][c] = 0.f;

    #pragma unroll
    for (int kk = 0; kk < 8; kk++) {
        const uint32_t kb = (uint32_t)kk * 32;
        uint32_t ah[2][4], bh[2][4], bl[2][4];
        #pragma unroll
        for (int mt = 0; mt < 2; mt++) {
            uint32_t ro = (uint32_t)(32*wr + 16*mt) * 272 + kb;
            LDM_X4(ah[mt], sb + TG_AH + aL_off + ro);
        }
        #pragma unroll
        for (int np = 0; np < 2; np++) {
            uint32_t no = (uint32_t)(32*wc + 16*np) * 272 + kb;
            LDM_X4(bh[np], sb + TG_WH + bL_off + no);
            LDM_X4(bl[np], sb + TG_WL + bL_off + no);
        }
        #pragma unroll
        for (int mt = 0; mt < 2; mt++)
            #pragma unroll
            for (int np = 0; np < 2; np++) {
                MMA_F16(acc[mt][2*np],   ah[mt], bh[np][0], bh[np][1]);
                MMA_F16(acc[mt][2*np+1], ah[mt], bh[np][2], bh[np][3]);
                MMA_F16(acc[mt][2*np],   ah[mt], bl[np][0], bl[np][1]);
                MMA_F16(acc[mt][2*np+1], ah[mt], bl[np][2], bl[np][3]);
            }
    }
    __syncthreads();

    {
        const int g = lid >> 2, t = lid & 3;
        #pragma unroll
        for (int mt = 0; mt < 2; mt++)
            #pragma unroll
            for (int nb = 0; nb < 4; nb++) {
                int e = 32*wr + 16*mt + g;
                int c = 32*wc + 8*nb + 2*t;
                *(float2*)&slab[e * TG_SLABS + c] = make_float2(acc[mt][nb][0], acc[mt][nb][1]);
                *(float2*)&slab[(e+8) * TG_SLABS + c] = make_float2(acc[mt][nb][2], acc[mt][nb][3]);
            }
    }
    __syncthreads();

    #pragma unroll
    for (int i = 0; i < 32; i++) {
        int idx = tid + 256 * i;
        int row = idx >> 7, col = idx & 127;
        size_t gpos = (size_t)(r0 + row) * FDIM + col;
        float o = slab[row * TG_SLABS + col] + b_sm[col];
        if (ADD) {
            float av = addp[gpos];
            o += MULVEC ? av * u_sm[col] : av;
        }
        if (OUTF32) outf[gpos] = o;
        if (OUTSPLIT) {
            float s = OSSP ? sspf(o) : o;
            oH[gpos] = __float2half_rn(s);
        }
    }
}

// =================================================================================
// Fused edge-filter GEMM + gather + attention — cp.async pipelined (R12 structure),
// single-fp16 B (32 MMAs/warp), fp16 slab + fp16 gather. 1 CTA/SM, 512 threads.
// =================================================================================
#define OFF_BH   0u              // 18432
#define OFF_U    18432u          // AH fp16 128x72x2=18432 | slab fp16 128x136x2=34816
#define OFF_AH   OFF_U
#define OFF_XPB  53248u          // gathered xjp fp16 [128][128] = 32768
#define OFF_STG  86016u          // rbf raw staging 32768
#define OFF_XI2  118784u         // 2 x 2048 (double-buffered xi, fp32)
#define OFF_PART 122880u         // float[2048]
#define OFF_ATT  131072u         // float[128]
#define OFF_JB   131584u         // 2 x 512 (double-buffered jidx)
#define SM_TOTAL 132608u
#define SLAB_H   136             // halves per slab row

__global__ void __launch_bounds__(512, 1) attn_mma(
    const float* __restrict__ rbf, const int* __restrict__ idxj,
    const float* __restrict__ k2f, const float* __restrict__ xi,
    const __half* __restrict__ xjph, float* __restrict__ mout,
    __half* __restrict__ oH)
{
    extern __shared__ char smem[];
    __half* AH = (__half*)(smem + OFF_AH);
    __half* BH = (__half*)(smem + OFF_BH);
    __half* slabh = (__half*)(smem + OFF_U);
    __half* xpbh  = (__half*)(smem + OFF_XPB);
    float* part   = (float*)(smem + OFF_PART);
    float* att_sm = (float*)(smem + OFF_ATT);

    const int tid = threadIdx.x;
    const int wid = tid >> 5, lid = tid & 31;
    const uint32_t sb = s2u(smem);

    // B = k2f, single fp16, once
    #pragma unroll
    for (int i = 0; i < 4; i++) {
        int fidx = tid + 512 * i;
        float4 v = ((const float4*)k2f)[fidx];
        int row = fidx >> 4, c = (fidx & 15) * 4;
        __half* dst = BH + row*72 + c;
        *(__half2*)(dst)     = __floats2half2_rn(v.x, v.y);
        *(__half2*)(dst + 2) = __floats2half2_rn(v.z, v.w);
    }

    const uint32_t aL = ((((lid & 7) + (lid & 8)) * 72) + ((lid & 16) ? 8 : 0)) * 2;
    const uint32_t bL = ((((lid & 7) + ((lid & 16) >> 1)) * 72) + ((lid & 8) ? 8 : 0)) * 2;
    const int wr = wid & 3, wc = wid >> 2;
    const int f  = tid & 127;
    const int q  = f >> 5;
    const int e0 = tid >> 7;
    const int stride = gridDim.x;

    auto stage = [&](int tile, int sel) {
        const char* rsrc = (const char*)(rbf + (size_t)tile * 8192);
        #pragma unroll
        for (int i = 0; i < 4; i++) {
            uint32_t o = (uint32_t)(tid + 512 * i) * 16u;
            CP16(sb + OFF_STG + o, rsrc + o);
        }
        if (tid < 128)
            CP16(sb + OFF_XI2 + (uint32_t)sel * 2048u + tid * 16u,
                 (const char*)(xi + (size_t)tile * 512) + tid * 16);
        if (tid < 32)
            CP16(sb + OFF_JB + (uint32_t)sel * 512u + tid * 16u,
                 (const char*)(idxj + tile * 128) + tid * 16);
    };
    // gather fp16 rows: each row = 256 B = 16 lanes x 16 B; 2 rows per warp-step
    auto gather = [&](int sel) {
        const int* jb = (const int*)(smem + OFF_JB + sel * 512);
        const int half_sel = lid >> 4;
        const uint32_t lane_off = (uint32_t)(lid & 15) * 16u;
        #pragma unroll
        for (int r = 0; r < 4; r++) {
            int e = wid * 8 + r * 2 + half_sel;
            int j = jb[e];
            CP16(sb + OFF_XPB + (uint32_t)e * 256u + lane_off,
                 (const char*)(xjph + (size_t)j * FDIM) + lane_off);
        }
    };

    int cur = 0;
    stage(blockIdx.x, 0);
    CP_COMMIT();
    CP_WAIT0();
    __syncthreads();
    gather(0);
    CP_COMMIT();

    for (int tile = blockIdx.x; tile < NTILES; tile += stride) {
        const int n0 = tile * 4;
        const int nxt = tile + stride;
        const bool has = nxt < NTILES;

        // A: fp32 staging -> single fp16
        #pragma unroll
        for (int i = 0; i < 4; i++) {
            int fidx = tid + 512 * i;
            float4 v = *(const float4*)(smem + OFF_STG + (uint32_t)fidx * 16u);
            int row = fidx >> 4, c = (fidx & 15) * 4;
            __half* dst = AH + row*72 + c;
            *(__half2*)(dst)     = __floats2half2_rn(v.x, v.y);
            *(__half2*)(dst + 2) = __floats2half2_rn(v.z, v.w);
        }
        if (has) stage(nxt, cur ^ 1);
        CP_COMMIT();
        __syncthreads();

        // MMA 128x128x64: D = A*B, single fp16 pass
        float acc[2][4][4];
        #pragma unroll
        for (int mt = 0; mt < 2; mt++)
            #pragma unroll
            for (int nb = 0; nb < 4; nb++)
                #pragma unroll
                for (int c = 0; c < 4; c++) acc[mt][nb][c] = 0.f;

        #pragma unroll
        for (int kk = 0; kk < 4; kk++) {
            const uint32_t kb = (uint32_t)kk * 32;
            uint32_t ah[2][4], bh[2][4];
            #pragma unroll
            for (int mt = 0; mt < 2; mt++) {
                uint32_t ro = (uint32_t)(32*wr + 16*mt) * 144 + kb;
                LDM_X4(ah[mt], sb + OFF_AH + aL + ro);
            }
            #pragma unroll
            for (int np = 0; np < 2; np++) {
                uint32_t no = (uint32_t)(32*wc + 16*np) * 144 + kb;
                LDM_X4(bh[np], sb + OFF_BH + bL + no);
            }
            #pragma unroll
            for (int mt = 0; mt < 2; mt++)
                #pragma unroll
                for (int np = 0; np < 2; np++) {
                    MMA_F16(acc[mt][2*np],   ah[mt], bh[np][0], bh[np][1]);
                    MMA_F16(acc[mt][2*np+1], ah[mt], bh[np][2], bh[np][3]);
                }
        }
        __syncthreads();   // A dead -> fp16 slab

        {
            const int g = lid >> 2, t = lid & 3;
            #pragma unroll
            for (int mt = 0; mt < 2; mt++)
                #pragma unroll
                for (int nb = 0; nb < 4; nb++) {
                    int e = 32*wr + 16*mt + g;
                    int c = 32*wc + 8*nb + 2*t;
                    *(__half2*)&slabh[e * SLAB_H + c] =
                        __floats2half2_rn(acc[mt][nb][0], acc[mt][nb][1]);
                    *(__half2*)&slabh[(e + 8) * SLAB_H + c] =
                        __floats2half2_rn(acc[mt][nb][2], acc[mt][nb][3]);
                }
        }
        CP_WAIT0();
        __syncthreads();

        const float* xi_c = (const float*)(smem + OFF_XI2 + (uint32_t)cur * 2048u);

        float xp[32];
        float lacc[4] = {0.f, 0.f, 0.f, 0.f};
        #pragma unroll
        for (int i = 0; i < 32; i++) {
            const int e = 4*i + e0;
            const int a = i >> 3;
            const int m = e & 31;
            float p = __half2float(slabh[e * SLAB_H + f]) * __half2float(xpbh[e * 128 + f]);
            xp[i] = p;
            lacc[a] += xi_c[a * FDIM + 4*m + q] * p;
        }
        #pragma unroll
        for (int a = 0; a < 4; a++)
            part[wid * 128 + a * 32 + lid] = lacc[a];
        __syncthreads();

        if (wid < 4) {
            float lg = 0.f;
            #pragma unroll
            for (int w2 = 0; w2 < 16; w2++) lg += part[w2 * 128 + wid * 32 + lid];
            float mx = lg;
            #pragma unroll
            for (int o = 16; o; o >>= 1) mx = fmaxf(mx, __shfl_xor_sync(0xffffffffu, mx, o));
            float ex = expf(lg - mx);
            float smv = ex;
            #pragma unroll
            for (int o = 16; o; o >>= 1) smv += __shfl_xor_sync(0xffffffffu, smv, o);
            att_sm[wid * 32 + lid] = ex / smv;
        }
        __syncthreads();

        float pacc[4] = {0.f, 0.f, 0.f, 0.f};
        #pragma unroll
        for (int i = 0; i < 32; i++) {
            const int e = 4*i + e0;
            const int a = i >> 3;
            const int m = e & 31;
            pacc[a] += att_sm[a * 32 + m] * xp[i];
        }
        #pragma unroll
        for (int a = 0; a < 4; a++)
            part[e0 * 512 + a * 128 + f] = pacc[a];
        __syncthreads();

        {
            size_t gpos = (size_t)n0 * FDIM + tid;
            float mv = xi_c[tid]
                + part[tid] + part[512 + tid] + part[1024 + tid] + part[1536 + tid];
            mout[gpos] = mv;
            oH[gpos] = __float2half_rn(sspf(mv));
        }

        if (has) gather(cur ^ 1);
        CP_COMMIT();
        __syncthreads();
        cur ^= 1;
    }
}

extern "C" void kernel_launch(void* const* d_in, const int* in_sizes, int n_in,
                              void* d_out, int out_size)
{
    const float* x    = (const float*)d_in[0];
    const float* rbf  = (const float*)d_in[1];
    const int*   idxj = (const int*)  d_in[3];
    const float* k2f  = (const float*)d_in[4];
    const float* wi   = (const float*)d_in[5];
    const float* bi   = (const float*)d_in[6];
    const float* wj   = (const float*)d_in[7];
    const float* bj   = (const float*)d_in[8];
    const float* rw1  = (const float*)d_in[9];
    const float* rb1  = (const float*)d_in[10];
    const float* rw2  = (const float*)d_in[11];
    const float* rb2  = (const float*)d_in[12];
    const float* wd   = (const float*)d_in[13];
    const float* bd   = (const float*)d_in[14];
    const float* u    = (const float*)d_in[15];
    float* out = (float*)d_out;

    float *xi_p, *m0_p, *m1_p;
    __half *xjpH, *wfH, *wfL, *tf, *sf;
    cudaGetSymbolAddress((void**)&xi_p,  g_xi);
    cudaGetSymbolAddress((void**)&m0_p,  g_m0);
    cudaGetSymbolAddress((void**)&m1_p,  g_m1);
    cudaGetSymbolAddress((void**)&xjpH,  g_xjpH);
    cudaGetSymbolAddress((void**)&wfH,   g_wfH);
    cudaGetSymbolAddress((void**)&wfL,   g_wfL);
    cudaGetSymbolAddress((void**)&tf,    g_tf);
    cudaGetSymbolAddress((void**)&sf,    g_sf);

    static int nsm = 0;
    if (nsm == 0) {
        cudaDeviceGetAttribute(&nsm, cudaDevAttrMultiProcessorCount, 0);
        if (nsm <= 0) nsm = 148;
        cudaFuncSetAttribute(attn_mma, cudaFuncAttributeMaxDynamicSharedMemorySize, SM_TOTAL);
        cudaFuncSetAttribute(tg2<0,false,false,true,false,false>,  cudaFuncAttributeMaxDynamicSharedMemorySize, TG_TOTAL);
        cudaFuncSetAttribute(tg2<0,false,false,false,true,false>,  cudaFuncAttributeMaxDynamicSharedMemorySize, TG_TOTAL);
        cudaFuncSetAttribute(tg2<1,false,false,false,true,false>,  cudaFuncAttributeMaxDynamicSharedMemorySize, TG_TOTAL);
        cudaFuncSetAttribute(tg2<1,true,false,true,true,true>,     cudaFuncAttributeMaxDynamicSharedMemorySize, TG_TOTAL);
        cudaFuncSetAttribute(tg2<1,true,false,false,true,true>,    cudaFuncAttributeMaxDynamicSharedMemorySize, TG_TOTAL);
        cudaFuncSetAttribute(tg2<1,true,true,true,false,false>,    cudaFuncAttributeMaxDynamicSharedMemorySize, TG_TOTAL);
    }

    const int TG_GRID = NROWS / 64;   // 512

    prep_w<<<112, 256>>>(wi, wj, rw1, rw2, wd, wfH, wfL);

    // xi = ssp(x)@wi.T+bi (fp32) ; xjp = ssp(x)@wj.T+bj (fp16 gather table)
    tg2<0,false,false,true,false,false><<<TG_GRID, 256, TG_TOTAL>>>(
        x, wfH, wfL, bi, nullptr, nullptr, xi_p, nullptr);
    tg2<0,false,false,false,true,false><<<TG_GRID, 256, TG_TOTAL>>>(
        x, wfH + 16384, wfL + 16384, bj, nullptr, nullptr, nullptr, xjpH);

    // m0 = attention; emits fp16 ssp(m0) -> sf
    attn_mma<<<nsm, 512, SM_TOTAL>>>(rbf, idxj, k2f, xi_p, xjpH, m0_p, sf);

    // res block 0
    tg2<1,false,false,false,true,false><<<TG_GRID, 256, TG_TOTAL>>>(
        sf, wfH + 2*16384, wfL + 2*16384, rb1, nullptr, nullptr, nullptr, tf);
    tg2<1,true,false,true,true,true><<<TG_GRID, 256, TG_TOTAL>>>(
        tf, wfH + 3*16384, wfL + 3*16384, rb2, m0_p, nullptr, m1_p, sf);

    // res block 1
    tg2<1,false,false,false,true,false><<<TG_GRID, 256, TG_TOTAL>>>(
        sf, wfH + 4*16384, wfL + 4*16384, rb1 + FDIM, nullptr, nullptr, nullptr, tf);
    tg2<1,true,false,false,true,true><<<TG_GRID, 256, TG_TOTAL>>>(
        tf, wfH + 5*16384, wfL + 5*16384, rb2 + FDIM, m1_p, nullptr, nullptr, sf);

    // out = u*x + ssp(m2)@wd+bd
    tg2<1,true,true,true,false,false><<<TG_GRID, 256, TG_TOTAL>>>(
        sf, wfH + 6*16384, wfL + 6*16384, bd, x, u, out, nullptr);
}

// round 15
// speedup vs baseline: 1.6433x; 1.0983x over previous
#include <cuda_runtime.h>
#include <cuda_bf16.h>
#include <cuda_fp16.h>
#include <cstdint>
#include <math.h>

#define NROWS 32768
#define FDIM  128
#define KDIM  64
#define MNBR  32
#define NTILES (NROWS/4)

// Scratch (allocation-free rule: __device__ globals)
__device__ float g_xi [NROWS*FDIM];
__device__ float g_m0 [NROWS*FDIM];
__device__ float g_m1 [NROWS*FDIM];
__device__ __align__(16) __half g_xjpH[NROWS*FDIM];  // xjp in fp16 (gather table)
__device__ __align__(16) __half g_wfH[7*16384];
__device__ __align__(16) __half g_wfL[7*16384];
__device__ __align__(16) __half g_sf[NROWS*FDIM];    // ssp-activation (fp16)

__device__ __forceinline__ float sspf(float a) {
    return fmaxf(a, 0.0f) + log1pf(expf(-fabsf(a))) - 0.69314718055994530942f;
}

// ---------------- mma.sync / cp.async helpers ----------------
__device__ __forceinline__ uint32_t s2u(const void* p) {
    uint32_t a;
    asm("{ .reg .u64 t; cvta.to.shared.u64 t, %1; cvt.u32.u64 %0, t; }" : "=r"(a) : "l"(p));
    return a;
}

#define LDM_X4(r, addr) \
    asm volatile("ldmatrix.sync.aligned.m8n8.x4.shared.b16 {%0,%1,%2,%3}, [%4];" \
        : "=r"((r)[0]), "=r"((r)[1]), "=r"((r)[2]), "=r"((r)[3]) : "r"(addr))

#define MMA_F16(d, a, b0, b1) \
    asm volatile("mma.sync.aligned.m16n8k16.row.col.f32.f16.f16.f32 " \
        "{%0,%1,%2,%3}, {%4,%5,%6,%7}, {%8,%9}, {%0,%1,%2,%3};" \
        : "+f"((d)[0]), "+f"((d)[1]), "+f"((d)[2]), "+f"((d)[3]) \
        : "r"((a)[0]), "r"((a)[1]), "r"((a)[2]), "r"((a)[3]), "r"(b0), "r"(b1))

#define CP16(dst, src) \
    asm volatile("cp.async.cg.shared.global [%0], [%1], 16;" :: "r"(dst), "l"(src) : "memory")
#define CP_COMMIT() asm volatile("cp.async.commit_group;" ::: "memory")
#define CP_WAIT0()  asm volatile("cp.async.wait_group 0;" ::: "memory")

__device__ __forceinline__ void f16_split4(float4 v, __half* H, __half* L) {
    __half h0 = __float2half_rn(v.x), h1 = __float2half_rn(v.y),
           h2 = __float2half_rn(v.z), h3 = __float2half_rn(v.w);
    *(__half2*)(H)     = __half2(h0, h1);
    *(__half2*)(H + 2) = __half2(h2, h3);
    *(__half2*)(L)     = __half2(__float2half_rn(v.x - __half2float(h0)),
                                 __float2half_rn(v.y - __half2float(h1)));
    *(__half2*)(L + 2) = __half2(__float2half_rn(v.z - __half2float(h2)),
                                 __float2half_rn(v.w - __half2float(h3)));
}

// ---------------- weight pre-split: 7 matrices of 128x128 (fp16 hi/lo) ----------------
__global__ void __launch_bounds__(256) prep_w(
    const float* __restrict__ wi, const float* __restrict__ wj,
    const float* __restrict__ rw1, const float* __restrict__ rw2,
    const float* __restrict__ wd,
    __half* __restrict__ WH, __half* __restrict__ WL)
{
    int idx = blockIdx.x * 256 + threadIdx.x;
    int mat = idx >> 12, off = idx & 4095;
    const float* src;
    switch (mat) {
        case 0: src = wi; break;
        case 1: src = wj; break;
        case 2: src = rw1; break;
        case 3: src = rw2; break;
        case 4: src = rw1 + 16384; break;
        case 5: src = rw2 + 16384; break;
        default: src = wd; break;
    }
    float4 v = ((const float4*)src)[off];
    size_t d = (size_t)mat * 16384 + (size_t)off * 4;
    f16_split4(v, WH + d, WL + d);
}

// =================================================================================
// Tensor-core row GEMM: W2P ? fp16 2-pass (hi/lo exact W) : single-pass fp16 W.
// 256 threads, 64x128 tile, 2 CTAs/SM.
// =================================================================================
#define TG_WH    0u
#define TG_WL    34816u
#define TG_U     69632u
#define TG_AH    TG_U
#define TG_BIAS  103424u
#define TG_MUL   103936u
#define TG_TOTAL 104448u
#define TG_SLABS 132

template<int AMODE, bool W2P, bool ADD, bool MULVEC, bool OUTF32, bool OUTSPLIT, bool OSSP>
__global__ __launch_bounds__(256, 2) void tg2(
    const void* __restrict__ aSrc,
    const __half* __restrict__ wHsrc, const __half* __restrict__ wLsrc,
    const float* __restrict__ bias, const float* __restrict__ addp,
    const float* __restrict__ mulv, float* __restrict__ outf,
    __half* __restrict__ oH)
{
    extern __shared__ char smem[];
    __half* AH = (__half*)(smem + TG_AH);
    float* slab = (float*)(smem + TG_U);
    float* b_sm = (float*)(smem + TG_BIAS);
    float* u_sm = (float*)(smem + TG_MUL);

    const int tid = threadIdx.x;
    const int wid = tid >> 5, lid = tid & 31;
    const uint32_t sb = s2u(smem);

    #pragma unroll
    for (int i = 0; i < 8; i++) {
        int idx = tid + 256 * i;
        int row = idx >> 4, c8 = idx & 15;
        *(uint4*)(smem + TG_WH + row * 272 + c8 * 16) = ((const uint4*)wHsrc)[idx];
        if (W2P)
            *(uint4*)(smem + TG_WL + row * 272 + c8 * 16) = ((const uint4*)wLsrc)[idx];
    }
    if (tid < 128) {
        b_sm[tid] = bias[tid];
        u_sm[tid] = MULVEC ? mulv[tid] : 0.0f;
    }

    const int r0 = blockIdx.x * 64;

    if (AMODE == 0) {
        #pragma unroll
        for (int i = 0; i < 8; i++) {
            int fidx = tid + 256 * i;
            float4 v = ((const float4*)((const float*)aSrc + (size_t)r0 * FDIM))[fidx];
            v.x = sspf(v.x); v.y = sspf(v.y); v.z = sspf(v.z); v.w = sspf(v.w);
            int row = fidx >> 5, c = (fidx & 31) * 4;
            __half* dst = AH + row * 136 + c;
            *(__half2*)(dst)     = __floats2half2_rn(v.x, v.y);
            *(__half2*)(dst + 2) = __floats2half2_rn(v.z, v.w);
        }
    } else {
        const uint4* a4 = (const uint4*)((const __half*)aSrc + (size_t)r0 * FDIM);
        #pragma unroll
        for (int i = 0; i < 4; i++) {
            int idx = tid + 256 * i;
            int row = idx >> 4, c8 = idx & 15;
            *(uint4*)(smem + TG_AH + row * 272 + c8 * 16) = a4[idx];
        }
    }
    __syncthreads();

    const uint32_t aL_off = (((lid & 7) + (lid & 8)) * 136 + ((lid & 16) ? 8 : 0)) * 2;
    const uint32_t bL_off = (((lid & 7) + ((lid & 16) >> 1)) * 136 + ((lid & 8) ? 8 : 0)) * 2;
    const int wr = wid & 1, wc = wid >> 1;

    float acc[2][4][4];
    #pragma unroll
    for (int mt = 0; mt < 2; mt++)
        #pragma unroll
        for (int nb = 0; nb < 4; nb++)
            #pragma unroll
            for (int c = 0; c < 4; c++) acc[mt][nb][c] = 0.f;

    #pragma unroll
    for (int kk = 0; kk < 8; kk++) {
        const uint32_t kb = (uint32_t)kk * 32;
        uint32_t ah[2][4], bh[2][4], bl[2][4];
        #pragma unroll
        for (int mt = 0; mt < 2; mt++) {
            uint32_t ro = (uint32_t)(32*wr + 16*mt) * 272 + kb;
            LDM_X4(ah[mt], sb + TG_AH + aL_off + ro);
        }
        #pragma unroll
        for (int np = 0; np < 2; np++) {
            uint32_t no = (uint32_t)(32*wc + 16*np) * 272 + kb;
            LDM_X4(bh[np], sb + TG_WH + bL_off + no);
            if (W2P) LDM_X4(bl[np], sb + TG_WL + bL_off + no);
        }
        #pragma unroll
        for (int mt = 0; mt < 2; mt++)
            #pragma unroll
            for (int np = 0; np < 2; np++) {
                MMA_F16(acc[mt][2*np],   ah[mt], bh[np][0], bh[np][1]);
                MMA_F16(acc[mt][2*np+1], ah[mt], bh[np][2], bh[np][3]);
                if (W2P) {
                    MMA_F16(acc[mt][2*np],   ah[mt], bl[np][0], bl[np][1]);
                    MMA_F16(acc[mt][2*np+1], ah[mt], bl[np][2], bl[np][3]);
                }
            }
    }
    __syncthreads();

    {
        const int g = lid >> 2, t = lid & 3;
        #pragma unroll
        for (int mt = 0; mt < 2; mt++)
            #pragma unroll
            for (int nb = 0; nb < 4; nb++) {
                int e = 32*wr + 16*mt + g;
                int c = 32*wc + 8*nb + 2*t;
                *(float2*)&slab[e * TG_SLABS + c] = make_float2(acc[mt][nb][0], acc[mt][nb][1]);
                *(float2*)&slab[(e+8) * TG_SLABS + c] = make_float2(acc[mt][nb][2], acc[mt][nb][3]);
            }
    }
    __syncthreads();

    #pragma unroll
    for (int i = 0; i < 32; i++) {
        int idx = tid + 256 * i;
        int row = idx >> 7, col = idx & 127;
        size_t gpos = (size_t)(r0 + row) * FDIM + col;
        float o = slab[row * TG_SLABS + col] + b_sm[col];
        if (ADD) {
            float av = addp[gpos];
            o += MULVEC ? av * u_sm[col] : av;
        }
        if (OUTF32) outf[gpos] = o;
        if (OUTSPLIT) {
            float s = OSSP ? sspf(o) : o;
            oH[gpos] = __float2half_rn(s);
        }
    }
}

// =================================================================================
// Fused residual block: m_out = m + (A@W1 + b1)@W2 + b2, A = sf fp16, t in smem.
// Single-fp16 W1/W2. 256 threads, 64-row tile, 2 CTAs/SM.
// =================================================================================
#define RF_W1    0u
#define RF_W2    34816u
#define RF_A     69632u           // fp16 64x136
#define RF_T     87040u           // fp16 64x136
#define RF_SLAB  RF_A             // fp32 64x132 = 33792, overlays A+T (dead after MMA2)
#define RF_B1    104448u
#define RF_B2    104960u
#define RF_TOTAL 105472u

template<bool OUTF32, bool OUTSPLIT>
__global__ __launch_bounds__(256, 2) void resfused(
    const __half* __restrict__ aSrc,
    const __half* __restrict__ w1src, const __half* __restrict__ w2src,
    const float* __restrict__ b1, const float* __restrict__ b2,
    const float* __restrict__ addp, float* __restrict__ outf,
    __half* __restrict__ oH)
{
    extern __shared__ char smem[];
    __half* Th = (__half*)(smem + RF_T);
    float* slab = (float*)(smem + RF_SLAB);
    float* b1s = (float*)(smem + RF_B1);
    float* b2s = (float*)(smem + RF_B2);

    const int tid = threadIdx.x;
    const int wid = tid >> 5, lid = tid & 31;
    const uint32_t sb = s2u(smem);

    // copy W1, W2 (2048 uint4 each)
    #pragma unroll
    for (int i = 0; i < 8; i++) {
        int idx = tid + 256 * i;
        int row = idx >> 4, c8 = idx & 15;
        *(uint4*)(smem + RF_W1 + row * 272 + c8 * 16) = ((const uint4*)w1src)[idx];
        *(uint4*)(smem + RF_W2 + row * 272 + c8 * 16) = ((const uint4*)w2src)[idx];
    }
    if (tid < 128) {
        b1s[tid] = b1[tid];
        b2s[tid] = b2[tid];
    }

    const int r0 = blockIdx.x * 64;

    // A tile (fp16 pre-converted): pure copy 1024 uint4
    {
        const uint4* a4 = (const uint4*)(aSrc + (size_t)r0 * FDIM);
        #pragma unroll
        for (int i = 0; i < 4; i++) {
            int idx = tid + 256 * i;
            int row = idx >> 4, c8 = idx & 15;
            *(uint4*)(smem + RF_A + row * 272 + c8 * 16) = a4[idx];
        }
    }
    __syncthreads();

    const uint32_t aL_off = (((lid & 7) + (lid & 8)) * 136 + ((lid & 16) ? 8 : 0)) * 2;
    const uint32_t bL_off = (((lid & 7) + ((lid & 16) >> 1)) * 136 + ((lid & 8) ? 8 : 0)) * 2;
    const int wr = wid & 1, wc = wid >> 1;
    const int g = lid >> 2, t4 = lid & 3;

    float acc[2][4][4];

    // ---- MMA1: t = A @ W1 ----
    #pragma unroll
    for (int mt = 0; mt < 2; mt++)
        #pragma unroll
        for (int nb = 0; nb < 4; nb++)
            #pragma unroll
            for (int c = 0; c < 4; c++) acc[mt][nb][c] = 0.f;

    #pragma unroll
    for (int kk = 0; kk < 8; kk++) {
        const uint32_t kb = (uint32_t)kk * 32;
        uint32_t ah[2][4], bh[2][4];
        #pragma unroll
        for (int mt = 0; mt < 2; mt++) {
            uint32_t ro = (uint32_t)(32*wr + 16*mt) * 272 + kb;
            LDM_X4(ah[mt], sb + RF_A + aL_off + ro);
        }
        #pragma unroll
        for (int np = 0; np < 2; np++) {
            uint32_t no = (uint32_t)(32*wc + 16*np) * 272 + kb;
            LDM_X4(bh[np], sb + RF_W1 + bL_off + no);
        }
        #pragma unroll
        for (int mt = 0; mt < 2; mt++)
            #pragma unroll
            for (int np = 0; np < 2; np++) {
                MMA_F16(acc[mt][2*np],   ah[mt], bh[np][0], bh[np][1]);
                MMA_F16(acc[mt][2*np+1], ah[mt], bh[np][2], bh[np][3]);
            }
    }

    // t (+b1) -> fp16 T in ldmatrix layout (T region untouched so far; no sync needed)
    #pragma unroll
    for (int mt = 0; mt < 2; mt++)
        #pragma unroll
        for (int nb = 0; nb < 4; nb++) {
            int e = 32*wr + 16*mt + g;
            int c = 32*wc + 8*nb + 2*t4;
            float bb0 = b1s[c], bb1 = b1s[c+1];
            *(__half2*)&Th[e * 136 + c] =
                __floats2half2_rn(acc[mt][nb][0] + bb0, acc[mt][nb][1] + bb1);
            *(__half2*)&Th[(e+8) * 136 + c] =
                __floats2half2_rn(acc[mt][nb][2] + bb0, acc[mt][nb][3] + bb1);
        }
    __syncthreads();   // T visible to all warps

    // ---- MMA2: d = T @ W2 ----
    #pragma unroll
    for (int mt = 0; mt < 2; mt++)
        #pragma unroll
        for (int nb = 0; nb < 4; nb++)
            #pragma unroll
            for (int c = 0; c < 4; c++) acc[mt][nb][c] = 0.f;

    #pragma unroll
    for (int kk = 0; kk < 8; kk++) {
        const uint32_t kb = (uint32_t)kk * 32;
        uint32_t ah[2][4], bh[2][4];
        #pragma unroll
        for (int mt = 0; mt < 2; mt++) {
            uint32_t ro = (uint32_t)(32*wr + 16*mt) * 272 + kb;
            LDM_X4(ah[mt], sb + RF_T + aL_off + ro);
        }
        #pragma unroll
        for (int np = 0; np < 2; np++) {
            uint32_t no = (uint32_t)(32*wc + 16*np) * 272 + kb;
            LDM_X4(bh[np], sb + RF_W2 + bL_off + no);
        }
        #pragma unroll
        for (int mt = 0; mt < 2; mt++)
            #pragma unroll
            for (int np = 0; np < 2; np++) {
                MMA_F16(acc[mt][2*np],   ah[mt], bh[np][0], bh[np][1]);
                MMA_F16(acc[mt][2*np+1], ah[mt], bh[np][2], bh[np][3]);
            }
    }
    __syncthreads();   // A/T dead -> fp32 slab overlays

    #pragma unroll
    for (int mt = 0; mt < 2; mt++)
        #pragma unroll
        for (int nb = 0; nb < 4; nb++) {
            int e = 32*wr + 16*mt + g;
            int c = 32*wc + 8*nb + 2*t4;
            *(float2*)&slab[e * TG_SLABS + c] = make_float2(acc[mt][nb][0], acc[mt][nb][1]);
            *(float2*)&slab[(e+8) * TG_SLABS + c] = make_float2(acc[mt][nb][2], acc[mt][nb][3]);
        }
    __syncthreads();

    #pragma unroll
    for (int i = 0; i < 32; i++) {
        int idx = tid + 256 * i;
        int row = idx >> 7, col = idx & 127;
        size_t gpos = (size_t)(r0 + row) * FDIM + col;
        float o = slab[row * TG_SLABS + col] + b2s[col] + addp[gpos];
        if (OUTF32) outf[gpos] = o;
        if (OUTSPLIT) oH[gpos] = __float2half_rn(sspf(o));
    }
}

// =================================================================================
// Fused edge-filter GEMM + gather + attention (validated R14, unchanged)
// =================================================================================
#define OFF_BH   0u
#define OFF_U    18432u
#define OFF_AH   OFF_U
#define OFF_XPB  53248u
#define OFF_STG  86016u
#define OFF_XI2  118784u
#define OFF_PART 122880u
#define OFF_ATT  131072u
#define OFF_JB   131584u
#define SM_TOTAL 132608u
#define SLAB_H   136

__global__ void __launch_bounds__(512, 1) attn_mma(
    const float* __restrict__ rbf, const int* __restrict__ idxj,
    const float* __restrict__ k2f, const float* __restrict__ xi,
    const __half* __restrict__ xjph, float* __restrict__ mout,
    __half* __restrict__ oH)
{
    extern __shared__ char smem[];
    __half* AH = (__half*)(smem + OFF_AH);
    __half* BH = (__half*)(smem + OFF_BH);
    __half* slabh = (__half*)(smem + OFF_U);
    __half* xpbh  = (__half*)(smem + OFF_XPB);
    float* part   = (float*)(smem + OFF_PART);
    float* att_sm = (float*)(smem + OFF_ATT);

    const int tid = threadIdx.x;
    const int wid = tid >> 5, lid = tid & 31;
    const uint32_t sb = s2u(smem);

    #pragma unroll
    for (int i = 0; i < 4; i++) {
        int fidx = tid + 512 * i;
        float4 v = ((const float4*)k2f)[fidx];
        int row = fidx >> 4, c = (fidx & 15) * 4;
        __half* dst = BH + row*72 + c;
        *(__half2*)(dst)     = __floats2half2_rn(v.x, v.y);
        *(__half2*)(dst + 2) = __floats2half2_rn(v.z, v.w);
    }

    const uint32_t aL = ((((lid & 7) + (lid & 8)) * 72) + ((lid & 16) ? 8 : 0)) * 2;
    const uint32_t bL = ((((lid & 7) + ((lid & 16) >> 1)) * 72) + ((lid & 8) ? 8 : 0)) * 2;
    const int wr = wid & 3, wc = wid >> 2;
    const int f  = tid & 127;
    const int q  = f >> 5;
    const int e0 = tid >> 7;
    const int stride = gridDim.x;

    auto stage = [&](int tile, int sel) {
        const char* rsrc = (const char*)(rbf + (size_t)tile * 8192);
        #pragma unroll
        for (int i = 0; i < 4; i++) {
            uint32_t o = (uint32_t)(tid + 512 * i) * 16u;
            CP16(sb + OFF_STG + o, rsrc + o);
        }
        if (tid < 128)
            CP16(sb + OFF_XI2 + (uint32_t)sel * 2048u + tid * 16u,
                 (const char*)(xi + (size_t)tile * 512) + tid * 16);
        if (tid < 32)
            CP16(sb + OFF_JB + (uint32_t)sel * 512u + tid * 16u,
                 (const char*)(idxj + tile * 128) + tid * 16);
    };
    auto gather = [&](int sel) {
        const int* jb = (const int*)(smem + OFF_JB + sel * 512);
        const int half_sel = lid >> 4;
        const uint32_t lane_off = (uint32_t)(lid & 15) * 16u;
        #pragma unroll
        for (int r = 0; r < 4; r++) {
            int e = wid * 8 + r * 2 + half_sel;
            int j = jb[e];
            CP16(sb + OFF_XPB + (uint32_t)e * 256u + lane_off,
                 (const char*)(xjph + (size_t)j * FDIM) + lane_off);
        }
    };

    int cur = 0;
    stage(blockIdx.x, 0);
    CP_COMMIT();
    CP_WAIT0();
    __syncthreads();
    gather(0);
    CP_COMMIT();

    for (int tile = blockIdx.x; tile < NTILES; tile += stride) {
        const int n0 = tile * 4;
        const int nxt = tile + stride;
        const bool has = nxt < NTILES;

        #pragma unroll
        for (int i = 0; i < 4; i++) {
            int fidx = tid + 512 * i;
            float4 v = *(const float4*)(smem + OFF_STG + (uint32_t)fidx * 16u);
            int row = fidx >> 4, c = (fidx & 15) * 4;
            __half* dst = AH + row*72 + c;
            *(__half2*)(dst)     = __floats2half2_rn(v.x, v.y);
            *(__half2*)(dst + 2) = __floats2half2_rn(v.z, v.w);
        }
        if (has) stage(nxt, cur ^ 1);
        CP_COMMIT();
        __syncthreads();

        float acc[2][4][4];
        #pragma unroll
        for (int mt = 0; mt < 2; mt++)
            #pragma unroll
            for (int nb = 0; nb < 4; nb++)
                #pragma unroll
                for (int c = 0; c < 4; c++) acc[mt][nb][c] = 0.f;

        #pragma unroll
        for (int kk = 0; kk < 4; kk++) {
            const uint32_t kb = (uint32_t)kk * 32;
            uint32_t ah[2][4], bh[2][4];
            #pragma unroll
            for (int mt = 0; mt < 2; mt++) {
                uint32_t ro = (uint32_t)(32*wr + 16*mt) * 144 + kb;
                LDM_X4(ah[mt], sb + OFF_AH + aL + ro);
            }
            #pragma unroll
            for (int np = 0; np < 2; np++) {
                uint32_t no = (uint32_t)(32*wc + 16*np) * 144 + kb;
                LDM_X4(bh[np], sb + OFF_BH + bL + no);
            }
            #pragma unroll
            for (int mt = 0; mt < 2; mt++)
                #pragma unroll
                for (int np = 0; np < 2; np++) {
                    MMA_F16(acc[mt][2*np],   ah[mt], bh[np][0], bh[np][1]);
                    MMA_F16(acc[mt][2*np+1], ah[mt], bh[np][2], bh[np][3]);
                }
        }
        __syncthreads();

        {
            const int g = lid >> 2, t = lid & 3;
            #pragma unroll
            for (int mt = 0; mt < 2; mt++)
                #pragma unroll
                for (int nb = 0; nb < 4; nb++) {
                    int e = 32*wr + 16*mt + g;
                    int c = 32*wc + 8*nb + 2*t;
                    *(__half2*)&slabh[e * SLAB_H + c] =
                        __floats2half2_rn(acc[mt][nb][0], acc[mt][nb][1]);
                    *(__half2*)&slabh[(e + 8) * SLAB_H + c] =
                        __floats2half2_rn(acc[mt][nb][2], acc[mt][nb][3]);
                }
        }
        CP_WAIT0();
        __syncthreads();

        const float* xi_c = (const float*)(smem + OFF_XI2 + (uint32_t)cur * 2048u);

        float xp[32];
        float lacc[4] = {0.f, 0.f, 0.f, 0.f};
        #pragma unroll
        for (int i = 0; i < 32; i++) {
            const int e = 4*i + e0;
            const int a = i >> 3;
            const int m = e & 31;
            float p = __half2float(slabh[e * SLAB_H + f]) * __half2float(xpbh[e * 128 + f]);
            xp[i] = p;
            lacc[a] += xi_c[a * FDIM + 4*m + q] * p;
        }
        #pragma unroll
        for (int a = 0; a < 4; a++)
            part[wid * 128 + a * 32 + lid] = lacc[a];
        __syncthreads();

        if (wid < 4) {
            float lg = 0.f;
            #pragma unroll
            for (int w2 = 0; w2 < 16; w2++) lg += part[w2 * 128 + wid * 32 + lid];
            float mx = lg;
            #pragma unroll
            for (int o = 16; o; o >>= 1) mx = fmaxf(mx, __shfl_xor_sync(0xffffffffu, mx, o));
            float ex = expf(lg - mx);
            float smv = ex;
            #pragma unroll
            for (int o = 16; o; o >>= 1) smv += __shfl_xor_sync(0xffffffffu, smv, o);
            att_sm[wid * 32 + lid] = ex / smv;
        }
        __syncthreads();

        float pacc[4] = {0.f, 0.f, 0.f, 0.f};
        #pragma unroll
        for (int i = 0; i < 32; i++) {
            const int e = 4*i + e0;
            const int a = i >> 3;
            const int m = e & 31;
            pacc[a] += att_sm[a * 32 + m] * xp[i];
        }
        #pragma unroll
        for (int a = 0; a < 4; a++)
            part[e0 * 512 + a * 128 + f] = pacc[a];
        __syncthreads();

        {
            size_t gpos = (size_t)n0 * FDIM + tid;
            float mv = xi_c[tid]
                + part[tid] + part[512 + tid] + part[1024 + tid] + part[1536 + tid];
            mout[gpos] = mv;
            oH[gpos] = __float2half_rn(sspf(mv));
        }

        if (has) gather(cur ^ 1);
        CP_COMMIT();
        __syncthreads();
        cur ^= 1;
    }
}

extern "C" void kernel_launch(void* const* d_in, const int* in_sizes, int n_in,
                              void* d_out, int out_size)
{
    const float* x    = (const float*)d_in[0];
    const float* rbf  = (const float*)d_in[1];
    const int*   idxj = (const int*)  d_in[3];
    const float* k2f  = (const float*)d_in[4];
    const float* wi   = (const float*)d_in[5];
    const float* bi   = (const float*)d_in[6];
    const float* wj   = (const float*)d_in[7];
    const float* bj   = (const float*)d_in[8];
    const float* rw1  = (const float*)d_in[9];
    const float* rb1  = (const float*)d_in[10];
    const float* rw2  = (const float*)d_in[11];
    const float* rb2  = (const float*)d_in[12];
    const float* wd   = (const float*)d_in[13];
    const float* bd   = (const float*)d_in[14];
    const float* u    = (const float*)d_in[15];
    float* out = (float*)d_out;

    float *xi_p, *m0_p, *m1_p;
    __half *xjpH, *wfH, *wfL, *sf;
    cudaGetSymbolAddress((void**)&xi_p,  g_xi);
    cudaGetSymbolAddress((void**)&m0_p,  g_m0);
    cudaGetSymbolAddress((void**)&m1_p,  g_m1);
    cudaGetSymbolAddress((void**)&xjpH,  g_xjpH);
    cudaGetSymbolAddress((void**)&wfH,   g_wfH);
    cudaGetSymbolAddress((void**)&wfL,   g_wfL);
    cudaGetSymbolAddress((void**)&sf,    g_sf);

    static int nsm = 0;
    if (nsm == 0) {
        cudaDeviceGetAttribute(&nsm, cudaDevAttrMultiProcessorCount, 0);
        if (nsm <= 0) nsm = 148;
        cudaFuncSetAttribute(attn_mma, cudaFuncAttributeMaxDynamicSharedMemorySize, SM_TOTAL);
        cudaFuncSetAttribute(tg2<0,true,false,false,true,false,false>,  cudaFuncAttributeMaxDynamicSharedMemorySize, TG_TOTAL);
        cudaFuncSetAttribute(tg2<0,true,false,false,false,true,false>,  cudaFuncAttributeMaxDynamicSharedMemorySize, TG_TOTAL);
        cudaFuncSetAttribute(tg2<1,false,true,true,true,false,false>,   cudaFuncAttributeMaxDynamicSharedMemorySize, TG_TOTAL);
        cudaFuncSetAttribute(resfused<true,true>,  cudaFuncAttributeMaxDynamicSharedMemorySize, RF_TOTAL);
        cudaFuncSetAttribute(resfused<false,true>, cudaFuncAttributeMaxDynamicSharedMemorySize, RF_TOTAL);
    }

    const int TG_GRID = NROWS / 64;   // 512

    prep_w<<<112, 256>>>(wi, wj, rw1, rw2, wd, wfH, wfL);

    // xi = ssp(x)@wi.T+bi (fp32, exact hi/lo W) ; xjp = ssp(x)@wj.T+bj (fp16)
    tg2<0,true,false,false,true,false,false><<<TG_GRID, 256, TG_TOTAL>>>(
        x, wfH, wfL, bi, nullptr, nullptr, xi_p, nullptr);
    tg2<0,true,false,false,false,true,false><<<TG_GRID, 256, TG_TOTAL>>>(
        x, wfH + 16384, wfL + 16384, bj, nullptr, nullptr, nullptr, xjpH);

    // m0 = attention; emits fp16 ssp(m0) -> sf
    attn_mma<<<nsm, 512, SM_TOTAL>>>(rbf, idxj, k2f, xi_p, xjpH, m0_p, sf);

    // fused residual blocks (t never leaves smem)
    resfused<true,true><<<TG_GRID, 256, RF_TOTAL>>>(
        sf, wfH + 2*16384, wfH + 3*16384, rb1, rb2, m0_p, m1_p, sf);
    resfused<false,true><<<TG_GRID, 256, RF_TOTAL>>>(
        sf, wfH + 4*16384, wfH + 5*16384, rb1 + FDIM, rb2 + FDIM, m1_p, nullptr, sf);

    // out = u*x + ssp(m2)@wd+bd   (single-pass fp16 W)
    tg2<1,false,true,true,true,false,false><<<TG_GRID, 256, TG_TOTAL>>>(
        sf, wfH + 6*16384, nullptr, bd, x, u, out, nullptr);
}

// round 16
// speedup vs baseline: 1.7738x; 1.0794x over previous
#include <cuda_runtime.h>
#include <cuda_bf16.h>
#include <cuda_fp16.h>
#include <cstdint>
#include <math.h>

#define NROWS 32768
#define FDIM  128
#define KDIM  64
#define MNBR  32
#define NTILES (NROWS/4)

// Scratch (allocation-free rule: __device__ globals)
__device__ float g_xi [NROWS*FDIM];
__device__ float g_m0 [NROWS*FDIM];
__device__ float g_m1 [NROWS*FDIM];
__device__ __align__(16) __half g_xjpH[NROWS*FDIM];
__device__ __align__(16) __half g_wfH[7*16384];
__device__ __align__(16) __half g_wfL[7*16384];
__device__ __align__(16) __half g_sf[NROWS*FDIM];

__device__ __forceinline__ float sspf(float a) {
    return fmaxf(a, 0.0f) + log1pf(expf(-fabsf(a))) - 0.69314718055994530942f;
}

// ---------------- mma.sync / cp.async helpers ----------------
__device__ __forceinline__ uint32_t s2u(const void* p) {
    uint32_t a;
    asm("{ .reg .u64 t; cvta.to.shared.u64 t, %1; cvt.u32.u64 %0, t; }" : "=r"(a) : "l"(p));
    return a;
}

#define LDM_X4(r, addr) \
    asm volatile("ldmatrix.sync.aligned.m8n8.x4.shared.b16 {%0,%1,%2,%3}, [%4];" \
        : "=r"((r)[0]), "=r"((r)[1]), "=r"((r)[2]), "=r"((r)[3]) : "r"(addr))

#define MMA_F16(d, a, b0, b1) \
    asm volatile("mma.sync.aligned.m16n8k16.row.col.f32.f16.f16.f32 " \
        "{%0,%1,%2,%3}, {%4,%5,%6,%7}, {%8,%9}, {%0,%1,%2,%3};" \
        : "+f"((d)[0]), "+f"((d)[1]), "+f"((d)[2]), "+f"((d)[3]) \
        : "r"((a)[0]), "r"((a)[1]), "r"((a)[2]), "r"((a)[3]), "r"(b0), "r"(b1))

#define CP16(dst, src) \
    asm volatile("cp.async.cg.shared.global [%0], [%1], 16;" :: "r"(dst), "l"(src) : "memory")
#define CP_COMMIT() asm volatile("cp.async.commit_group;" ::: "memory")
#define CP_WAIT0()  asm volatile("cp.async.wait_group 0;" ::: "memory")

__device__ __forceinline__ void f16_split4(float4 v, __half* H, __half* L) {
    __half h0 = __float2half_rn(v.x), h1 = __float2half_rn(v.y),
           h2 = __float2half_rn(v.z), h3 = __float2half_rn(v.w);
    *(__half2*)(H)     = __half2(h0, h1);
    *(__half2*)(H + 2) = __half2(h2, h3);
    *(__half2*)(L)     = __half2(__float2half_rn(v.x - __half2float(h0)),
                                 __float2half_rn(v.y - __half2float(h1)));
    *(__half2*)(L + 2) = __half2(__float2half_rn(v.z - __half2float(h2)),
                                 __float2half_rn(v.w - __half2float(h3)));
}

// ---------------- weight pre-split ----------------
__global__ void __launch_bounds__(256) prep_w(
    const float* __restrict__ wi, const float* __restrict__ wj,
    const float* __restrict__ rw1, const float* __restrict__ rw2,
    const float* __restrict__ wd,
    __half* __restrict__ WH, __half* __restrict__ WL)
{
    int idx = blockIdx.x * 256 + threadIdx.x;
    int mat = idx >> 12, off = idx & 4095;
    const float* src;
    switch (mat) {
        case 0: src = wi; break;
        case 1: src = wj; break;
        case 2: src = rw1; break;
        case 3: src = rw2; break;
        case 4: src = rw1 + 16384; break;
        case 5: src = rw2 + 16384; break;
        default: src = wd; break;
    }
    float4 v = ((const float4*)src)[off];
    size_t d = (size_t)mat * 16384 + (size_t)off * 4;
    f16_split4(v, WH + d, WL + d);
}

// =================================================================================
// Tensor-core row GEMM (validated R15)
// =================================================================================
#define TG_WH    0u
#define TG_WL    34816u
#define TG_U     69632u
#define TG_AH    TG_U
#define TG_BIAS  103424u
#define TG_MUL   103936u
#define TG_TOTAL 104448u
#define TG_SLABS 132

template<int AMODE, bool W2P, bool ADD, bool MULVEC, bool OUTF32, bool OUTSPLIT, bool OSSP>
__global__ __launch_bounds__(256, 2) void tg2(
    const void* __restrict__ aSrc,
    const __half* __restrict__ wHsrc, const __half* __restrict__ wLsrc,
    const float* __restrict__ bias, const float* __restrict__ addp,
    const float* __restrict__ mulv, float* __restrict__ outf,
    __half* __restrict__ oH)
{
    extern __shared__ char smem[];
    __half* AH = (__half*)(smem + TG_AH);
    float* slab = (float*)(smem + TG_U);
    float* b_sm = (float*)(smem + TG_BIAS);
    float* u_sm = (float*)(smem + TG_MUL);

    const int tid = threadIdx.x;
    const int wid = tid >> 5, lid = tid & 31;
    const uint32_t sb = s2u(smem);

    #pragma unroll
    for (int i = 0; i < 8; i++) {
        int idx = tid + 256 * i;
        int row = idx >> 4, c8 = idx & 15;
        *(uint4*)(smem + TG_WH + row * 272 + c8 * 16) = ((const uint4*)wHsrc)[idx];
        if (W2P)
            *(uint4*)(smem + TG_WL + row * 272 + c8 * 16) = ((const uint4*)wLsrc)[idx];
    }
    if (tid < 128) {
        b_sm[tid] = bias[tid];
        u_sm[tid] = MULVEC ? mulv[tid] : 0.0f;
    }

    const int r0 = blockIdx.x * 64;

    if (AMODE == 0) {
        #pragma unroll
        for (int i = 0; i < 8; i++) {
            int fidx = tid + 256 * i;
            float4 v = ((const float4*)((const float*)aSrc + (size_t)r0 * FDIM))[fidx];
            v.x = sspf(v.x); v.y = sspf(v.y); v.z = sspf(v.z); v.w = sspf(v.w);
            int row = fidx >> 5, c = (fidx & 31) * 4;
            __half* dst = AH + row * 136 + c;
            *(__half2*)(dst)     = __floats2half2_rn(v.x, v.y);
            *(__half2*)(dst + 2) = __floats2half2_rn(v.z, v.w);
        }
    } else {
        const uint4* a4 = (const uint4*)((const __half*)aSrc + (size_t)r0 * FDIM);
        #pragma unroll
        for (int i = 0; i < 4; i++) {
            int idx = tid + 256 * i;
            int row = idx >> 4, c8 = idx & 15;
            *(uint4*)(smem + TG_AH + row * 272 + c8 * 16) = a4[idx];
        }
    }
    __syncthreads();

    const uint32_t aL_off = (((lid & 7) + (lid & 8)) * 136 + ((lid & 16) ? 8 : 0)) * 2;
    const uint32_t bL_off = (((lid & 7) + ((lid & 16) >> 1)) * 136 + ((lid & 8) ? 8 : 0)) * 2;
    const int wr = wid & 1, wc = wid >> 1;

    float acc[2][4][4];
    #pragma unroll
    for (int mt = 0; mt < 2; mt++)
        #pragma unroll
        for (int nb = 0; nb < 4; nb++)
            #pragma unroll
            for (int c = 0; c < 4; c++) acc[mt][nb][c] = 0.f;

    #pragma unroll
    for (int kk = 0; kk < 8; kk++) {
        const uint32_t kb = (uint32_t)kk * 32;
        uint32_t ah[2][4], bh[2][4], bl[2][4];
        #pragma unroll
        for (int mt = 0; mt < 2; mt++) {
            uint32_t ro = (uint32_t)(32*wr + 16*mt) * 272 + kb;
            LDM_X4(ah[mt], sb + TG_AH + aL_off + ro);
        }
        #pragma unroll
        for (int np = 0; np < 2; np++) {
            uint32_t no = (uint32_t)(32*wc + 16*np) * 272 + kb;
            LDM_X4(bh[np], sb + TG_WH + bL_off + no);
            if (W2P) LDM_X4(bl[np], sb + TG_WL + bL_off + no);
        }
        #pragma unroll
        for (int mt = 0; mt < 2; mt++)
            #pragma unroll
            for (int np = 0; np < 2; np++) {
                MMA_F16(acc[mt][2*np],   ah[mt], bh[np][0], bh[np][1]);
                MMA_F16(acc[mt][2*np+1], ah[mt], bh[np][2], bh[np][3]);
                if (W2P) {
                    MMA_F16(acc[mt][2*np],   ah[mt], bl[np][0], bl[np][1]);
                    MMA_F16(acc[mt][2*np+1], ah[mt], bl[np][2], bl[np][3]);
                }
            }
    }
    __syncthreads();

    {
        const int g = lid >> 2, t = lid & 3;
        #pragma unroll
        for (int mt = 0; mt < 2; mt++)
            #pragma unroll
            for (int nb = 0; nb < 4; nb++) {
                int e = 32*wr + 16*mt + g;
                int c = 32*wc + 8*nb + 2*t;
                *(float2*)&slab[e * TG_SLABS + c] = make_float2(acc[mt][nb][0], acc[mt][nb][1]);
                *(float2*)&slab[(e+8) * TG_SLABS + c] = make_float2(acc[mt][nb][2], acc[mt][nb][3]);
            }
    }
    __syncthreads();

    #pragma unroll
    for (int i = 0; i < 32; i++) {
        int idx = tid + 256 * i;
        int row = idx >> 7, col = idx & 127;
        size_t gpos = (size_t)(r0 + row) * FDIM + col;
        float o = slab[row * TG_SLABS + col] + b_sm[col];
        if (ADD) {
            float av = addp[gpos];
            o += MULVEC ? av * u_sm[col] : av;
        }
        if (OUTF32) outf[gpos] = o;
        if (OUTSPLIT) {
            float s = OSSP ? sspf(o) : o;
            oH[gpos] = __float2half_rn(s);
        }
    }
}

// =================================================================================
// Fused residual block (validated R15)
// =================================================================================
#define RF_W1    0u
#define RF_W2    34816u
#define RF_A     69632u
#define RF_T     87040u
#define RF_SLAB  RF_A
#define RF_B1    104448u
#define RF_B2    104960u
#define RF_TOTAL 105472u

template<bool OUTF32, bool OUTSPLIT>
__global__ __launch_bounds__(256, 2) void resfused(
    const __half* __restrict__ aSrc,
    const __half* __restrict__ w1src, const __half* __restrict__ w2src,
    const float* __restrict__ b1, const float* __restrict__ b2,
    const float* __restrict__ addp, float* __restrict__ outf,
    __half* __restrict__ oH)
{
    extern __shared__ char smem[];
    __half* Th = (__half*)(smem + RF_T);
    float* slab = (float*)(smem + RF_SLAB);
    float* b1s = (float*)(smem + RF_B1);
    float* b2s = (float*)(smem + RF_B2);

    const int tid = threadIdx.x;
    const int wid = tid >> 5, lid = tid & 31;
    const uint32_t sb = s2u(smem);

    #pragma unroll
    for (int i = 0; i < 8; i++) {
        int idx = tid + 256 * i;
        int row = idx >> 4, c8 = idx & 15;
        *(uint4*)(smem + RF_W1 + row * 272 + c8 * 16) = ((const uint4*)w1src)[idx];
        *(uint4*)(smem + RF_W2 + row * 272 + c8 * 16) = ((const uint4*)w2src)[idx];
    }
    if (tid < 128) {
        b1s[tid] = b1[tid];
        b2s[tid] = b2[tid];
    }

    const int r0 = blockIdx.x * 64;

    {
        const uint4* a4 = (const uint4*)(aSrc + (size_t)r0 * FDIM);
        #pragma unroll
        for (int i = 0; i < 4; i++) {
            int idx = tid + 256 * i;
            int row = idx >> 4, c8 = idx & 15;
            *(uint4*)(smem + RF_A + row * 272 + c8 * 16) = a4[idx];
        }
    }
    __syncthreads();

    const uint32_t aL_off = (((lid & 7) + (lid & 8)) * 136 + ((lid & 16) ? 8 : 0)) * 2;
    const uint32_t bL_off = (((lid & 7) + ((lid & 16) >> 1)) * 136 + ((lid & 8) ? 8 : 0)) * 2;
    const int wr = wid & 1, wc = wid >> 1;
    const int g = lid >> 2, t4 = lid & 3;

    float acc[2][4][4];

    #pragma unroll
    for (int mt = 0; mt < 2; mt++)
        #pragma unroll
        for (int nb = 0; nb < 4; nb++)
            #pragma unroll
            for (int c = 0; c < 4; c++) acc[mt][nb][c] = 0.f;

    #pragma unroll
    for (int kk = 0; kk < 8; kk++) {
        const uint32_t kb = (uint32_t)kk * 32;
        uint32_t ah[2][4], bh[2][4];
        #pragma unroll
        for (int mt = 0; mt < 2; mt++) {
            uint32_t ro = (uint32_t)(32*wr + 16*mt) * 272 + kb;
            LDM_X4(ah[mt], sb + RF_A + aL_off + ro);
        }
        #pragma unroll
        for (int np = 0; np < 2; np++) {
            uint32_t no = (uint32_t)(32*wc + 16*np) * 272 + kb;
            LDM_X4(bh[np], sb + RF_W1 + bL_off + no);
        }
        #pragma unroll
        for (int mt = 0; mt < 2; mt++)
            #pragma unroll
            for (int np = 0; np < 2; np++) {
                MMA_F16(acc[mt][2*np],   ah[mt], bh[np][0], bh[np][1]);
                MMA_F16(acc[mt][2*np+1], ah[mt], bh[np][2], bh[np][3]);
            }
    }

    #pragma unroll
    for (int mt = 0; mt < 2; mt++)
        #pragma unroll
        for (int nb = 0; nb < 4; nb++) {
            int e = 32*wr + 16*mt + g;
            int c = 32*wc + 8*nb + 2*t4;
            float bb0 = b1s[c], bb1 = b1s[c+1];
            *(__half2*)&Th[e * 136 + c] =
                __floats2half2_rn(acc[mt][nb][0] + bb0, acc[mt][nb][1] + bb1);
            *(__half2*)&Th[(e+8) * 136 + c] =
                __floats2half2_rn(acc[mt][nb][2] + bb0, acc[mt][nb][3] + bb1);
        }
    __syncthreads();

    #pragma unroll
    for (int mt = 0; mt < 2; mt++)
        #pragma unroll
        for (int nb = 0; nb < 4; nb++)
            #pragma unroll
            for (int c = 0; c < 4; c++) acc[mt][nb][c] = 0.f;

    #pragma unroll
    for (int kk = 0; kk < 8; kk++) {
        const uint32_t kb = (uint32_t)kk * 32;
        uint32_t ah[2][4], bh[2][4];
        #pragma unroll
        for (int mt = 0; mt < 2; mt++) {
            uint32_t ro = (uint32_t)(32*wr + 16*mt) * 272 + kb;
            LDM_X4(ah[mt], sb + RF_T + aL_off + ro);
        }
        #pragma unroll
        for (int np = 0; np < 2; np++) {
            uint32_t no = (uint32_t)(32*wc + 16*np) * 272 + kb;
            LDM_X4(bh[np], sb + RF_W2 + bL_off + no);
        }
        #pragma unroll
        for (int mt = 0; mt < 2; mt++)
            #pragma unroll
            for (int np = 0; np < 2; np++) {
                MMA_F16(acc[mt][2*np],   ah[mt], bh[np][0], bh[np][1]);
                MMA_F16(acc[mt][2*np+1], ah[mt], bh[np][2], bh[np][3]);
            }
    }
    __syncthreads();

    #pragma unroll
    for (int mt = 0; mt < 2; mt++)
        #pragma unroll
        for (int nb = 0; nb < 4; nb++) {
            int e = 32*wr + 16*mt + g;
            int c = 32*wc + 8*nb + 2*t4;
            *(float2*)&slab[e * TG_SLABS + c] = make_float2(acc[mt][nb][0], acc[mt][nb][1]);
            *(float2*)&slab[(e+8) * TG_SLABS + c] = make_float2(acc[mt][nb][2], acc[mt][nb][3]);
        }
    __syncthreads();

    #pragma unroll
    for (int i = 0; i < 32; i++) {
        int idx = tid + 256 * i;
        int row = idx >> 7, col = idx & 127;
        size_t gpos = (size_t)(r0 + row) * FDIM + col;
        float o = slab[row * TG_SLABS + col] + b2s[col] + addp[gpos];
        if (OUTF32) outf[gpos] = o;
        if (OUTSPLIT) oH[gpos] = __float2half_rn(sspf(o));
    }
}

// =================================================================================
// Fused edge-filter GEMM + gather + attention — half2 column-pair epilogue.
// =================================================================================
#define OFF_BH    0u
#define OFF_U     18432u
#define OFF_AH    OFF_U
#define OFF_XPB   53248u
#define OFF_STG   86016u
#define OFF_XI2   118784u
#define OFF_PARTL 122880u        // float[128*33] = 16896 B (logit partials, padded)
#define OFF_PARTP 139776u        // float[8*512]  = 16384 B (output partials)
#define OFF_ATT   156160u        // float[128]
#define OFF_JB    156672u        // 2 x 512
#define SM_TOTAL  157696u
#define SLAB_H    136

__global__ void __launch_bounds__(512, 1) attn_mma(
    const float* __restrict__ rbf, const int* __restrict__ idxj,
    const float* __restrict__ k2f, const float* __restrict__ xi,
    const __half* __restrict__ xjph, float* __restrict__ mout,
    __half* __restrict__ oH)
{
    extern __shared__ char smem[];
    __half* AH = (__half*)(smem + OFF_AH);
    __half* BH = (__half*)(smem + OFF_BH);
    __half* slabh = (__half*)(smem + OFF_U);
    __half* xpbh  = (__half*)(smem + OFF_XPB);
    float* partL  = (float*)(smem + OFF_PARTL);
    float* partP  = (float*)(smem + OFF_PARTP);
    float* att_sm = (float*)(smem + OFF_ATT);

    const int tid = threadIdx.x;
    const int wid = tid >> 5, lid = tid & 31;
    const uint32_t sb = s2u(smem);

    // B = k2f, single fp16, once
    #pragma unroll
    for (int i = 0; i < 4; i++) {
        int fidx = tid + 512 * i;
        float4 v = ((const float4*)k2f)[fidx];
        int row = fidx >> 4, c = (fidx & 15) * 4;
        __half* dst = BH + row*72 + c;
        *(__half2*)(dst)     = __floats2half2_rn(v.x, v.y);
        *(__half2*)(dst + 2) = __floats2half2_rn(v.z, v.w);
    }

    const uint32_t aL = ((((lid & 7) + (lid & 8)) * 72) + ((lid & 16) ? 8 : 0)) * 2;
    const uint32_t bL = ((((lid & 7) + ((lid & 16) >> 1)) * 72) + ((lid & 8) ? 8 : 0)) * 2;
    const int wr = wid & 3, wc = wid >> 2;
    // epilogue mapping: 8 edge-groups x 64 column-pairs
    const int e0  = tid >> 6;            // 0..7
    const int cpi = tid & 63;            // column-pair index
    const int c0  = cpi * 2;             // even column
    const int q   = cpi >> 4;            // c0 >> 5 (same for c0, c0+1)
    const int mmE = (cpi & 15) * 2;      // even logit slot; odd = mmE+1
    const int ctb = e0 * 4 + q;          // contributor index (0..31)
    const int stride = gridDim.x;

    auto stage = [&](int tile, int sel) {
        const char* rsrc = (const char*)(rbf + (size_t)tile * 8192);
        #pragma unroll
        for (int i = 0; i < 4; i++) {
            uint32_t o = (uint32_t)(tid + 512 * i) * 16u;
            CP16(sb + OFF_STG + o, rsrc + o);
        }
        if (tid < 128)
            CP16(sb + OFF_XI2 + (uint32_t)sel * 2048u + tid * 16u,
                 (const char*)(xi + (size_t)tile * 512) + tid * 16);
        if (tid < 32)
            CP16(sb + OFF_JB + (uint32_t)sel * 512u + tid * 16u,
                 (const char*)(idxj + tile * 128) + tid * 16);
    };
    auto gather = [&](int sel) {
        const int* jb = (const int*)(smem + OFF_JB + sel * 512);
        const int half_sel = lid >> 4;
        const uint32_t lane_off = (uint32_t)(lid & 15) * 16u;
        #pragma unroll
        for (int r = 0; r < 4; r++) {
            int e = wid * 8 + r * 2 + half_sel;
            int j = jb[e];
            CP16(sb + OFF_XPB + (uint32_t)e * 256u + lane_off,
                 (const char*)(xjph + (size_t)j * FDIM) + lane_off);
        }
    };

    int cur = 0;
    stage(blockIdx.x, 0);
    CP_COMMIT();
    CP_WAIT0();
    __syncthreads();
    gather(0);
    CP_COMMIT();

    for (int tile = blockIdx.x; tile < NTILES; tile += stride) {
        const int n0 = tile * 4;
        const int nxt = tile + stride;
        const bool has = nxt < NTILES;

        // A: fp32 staging -> single fp16
        #pragma unroll
        for (int i = 0; i < 4; i++) {
            int fidx = tid + 512 * i;
            float4 v = *(const float4*)(smem + OFF_STG + (uint32_t)fidx * 16u);
            int row = fidx >> 4, c = (fidx & 15) * 4;
            __half* dst = AH + row*72 + c;
            *(__half2*)(dst)     = __floats2half2_rn(v.x, v.y);
            *(__half2*)(dst + 2) = __floats2half2_rn(v.z, v.w);
        }
        if (has) stage(nxt, cur ^ 1);
        CP_COMMIT();
        __syncthreads();

        // MMA 128x128x64: D = A*B, single fp16 pass
        float acc[2][4][4];
        #pragma unroll
        for (int mt = 0; mt < 2; mt++)
            #pragma unroll
            for (int nb = 0; nb < 4; nb++)
                #pragma unroll
                for (int c = 0; c < 4; c++) acc[mt][nb][c] = 0.f;

        #pragma unroll
        for (int kk = 0; kk < 4; kk++) {
            const uint32_t kb = (uint32_t)kk * 32;
            uint32_t ah[2][4], bh[2][4];
            #pragma unroll
            for (int mt = 0; mt < 2; mt++) {
                uint32_t ro = (uint32_t)(32*wr + 16*mt) * 144 + kb;
                LDM_X4(ah[mt], sb + OFF_AH + aL + ro);
            }
            #pragma unroll
            for (int np = 0; np < 2; np++) {
                uint32_t no = (uint32_t)(32*wc + 16*np) * 144 + kb;
                LDM_X4(bh[np], sb + OFF_BH + bL + no);
            }
            #pragma unroll
            for (int mt = 0; mt < 2; mt++)
                #pragma unroll
                for (int np = 0; np < 2; np++) {
                    MMA_F16(acc[mt][2*np],   ah[mt], bh[np][0], bh[np][1]);
                    MMA_F16(acc[mt][2*np+1], ah[mt], bh[np][2], bh[np][3]);
                }
        }
        __syncthreads();   // A dead -> fp16 slab

        {
            const int g = lid >> 2, t = lid & 3;
            #pragma unroll
            for (int mt = 0; mt < 2; mt++)
                #pragma unroll
                for (int nb = 0; nb < 4; nb++) {
                    int e = 32*wr + 16*mt + g;
                    int c = 32*wc + 8*nb + 2*t;
                    *(__half2*)&slabh[e * SLAB_H + c] =
                        __floats2half2_rn(acc[mt][nb][0], acc[mt][nb][1]);
                    *(__half2*)&slabh[(e + 8) * SLAB_H + c] =
                        __floats2half2_rn(acc[mt][nb][2], acc[mt][nb][3]);
                }
        }
        CP_WAIT0();
        __syncthreads();

        const float* xi_c = (const float*)(smem + OFF_XI2 + (uint32_t)cur * 2048u);

        // product + logit partials: 16 edges x 2 columns per thread (half2)
        __half2 xp2[16];
        float lE[4] = {0.f, 0.f, 0.f, 0.f};
        float lO[4] = {0.f, 0.f, 0.f, 0.f};
        #pragma unroll
        for (int i = 0; i < 16; i++) {
            const int e = 8*i + e0;
            const int a = i >> 2;            // compile-time per unrolled i
            const int m = e & 31;
            __half2 s2 = *(const __half2*)&slabh[e * SLAB_H + c0];
            __half2 x2 = *(const __half2*)&xpbh[e * 128 + c0];
            __half2 p2 = __hmul2(s2, x2);
            xp2[i] = p2;
            float2 pf = __half22float2(p2);
            float w = xi_c[a * FDIM + 4*m + q];
            lE[a] += w * pf.x;
            lO[a] += w * pf.y;
        }
        #pragma unroll
        for (int a = 0; a < 4; a++) {
            partL[(a*32 + mmE)     * 33 + ctb] = lE[a];
            partL[(a*32 + mmE + 1) * 33 + ctb] = lO[a];
        }
        __syncthreads();

        // logits reduction + softmax: thread s (0..127) owns slot (a = s>>5, mm = s&31)
        if (tid < 128) {
            float lg = 0.f;
            #pragma unroll
            for (int c2 = 0; c2 < 32; c2++) lg += partL[tid * 33 + c2];
            float mx = lg;
            #pragma unroll
            for (int o = 16; o; o >>= 1) mx = fmaxf(mx, __shfl_xor_sync(0xffffffffu, mx, o));
            float ex = expf(lg - mx);
            float smv = ex;
            #pragma unroll
            for (int o = 16; o; o >>= 1) smv += __shfl_xor_sync(0xffffffffu, smv, o);
            att_sm[tid] = ex / smv;
        }
        __syncthreads();

        // attention-weighted sum from packed products
        float pE[4] = {0.f, 0.f, 0.f, 0.f};
        float pO[4] = {0.f, 0.f, 0.f, 0.f};
        #pragma unroll
        for (int i = 0; i < 16; i++) {
            const int e = 8*i + e0;
            const int a = i >> 2;
            const int m = e & 31;
            float w = att_sm[a * 32 + m];
            float2 pf = __half22float2(xp2[i]);
            pE[a] += w * pf.x;
            pO[a] += w * pf.y;
        }
        #pragma unroll
        for (int a = 0; a < 4; a++)
            *(float2*)&partP[e0 * 512 + a * 128 + c0] = make_float2(pE[a], pO[a]);
        __syncthreads();

        {
            size_t gpos = (size_t)n0 * FDIM + tid;
            float mv = xi_c[tid];
            #pragma unroll
            for (int g2 = 0; g2 < 8; g2++) mv += partP[g2 * 512 + tid];
            mout[gpos] = mv;
            oH[gpos] = __float2half_rn(sspf(mv));
        }

        if (has) gather(cur ^ 1);
        CP_COMMIT();
        __syncthreads();
        cur ^= 1;
    }
}

extern "C" void kernel_launch(void* const* d_in, const int* in_sizes, int n_in,
                              void* d_out, int out_size)
{
    const float* x    = (const float*)d_in[0];
    const float* rbf  = (const float*)d_in[1];
    const int*   idxj = (const int*)  d_in[3];
    const float* k2f  = (const float*)d_in[4];
    const float* wi   = (const float*)d_in[5];
    const float* bi   = (const float*)d_in[6];
    const float* wj   = (const float*)d_in[7];
    const float* bj   = (const float*)d_in[8];
    const float* rw1  = (const float*)d_in[9];
    const float* rb1  = (const float*)d_in[10];
    const float* rw2  = (const float*)d_in[11];
    const float* rb2  = (const float*)d_in[12];
    const float* wd   = (const float*)d_in[13];
    const float* bd   = (const float*)d_in[14];
    const float* u    = (const float*)d_in[15];
    float* out = (float*)d_out;

    float *xi_p, *m0_p, *m1_p;
    __half *xjpH, *wfH, *wfL, *sf;
    cudaGetSymbolAddress((void**)&xi_p,  g_xi);
    cudaGetSymbolAddress((void**)&m0_p,  g_m0);
    cudaGetSymbolAddress((void**)&m1_p,  g_m1);
    cudaGetSymbolAddress((void**)&xjpH,  g_xjpH);
    cudaGetSymbolAddress((void**)&wfH,   g_wfH);
    cudaGetSymbolAddress((void**)&wfL,   g_wfL);
    cudaGetSymbolAddress((void**)&sf,    g_sf);

    static int nsm = 0;
    if (nsm == 0) {
        cudaDeviceGetAttribute(&nsm, cudaDevAttrMultiProcessorCount, 0);
        if (nsm <= 0) nsm = 148;
        cudaFuncSetAttribute(attn_mma, cudaFuncAttributeMaxDynamicSharedMemorySize, SM_TOTAL);
        cudaFuncSetAttribute(tg2<0,true,false,false,true,false,false>,  cudaFuncAttributeMaxDynamicSharedMemorySize, TG_TOTAL);
        cudaFuncSetAttribute(tg2<0,true,false,false,false,true,false>,  cudaFuncAttributeMaxDynamicSharedMemorySize, TG_TOTAL);
        cudaFuncSetAttribute(tg2<1,false,true,true,true,false,false>,   cudaFuncAttributeMaxDynamicSharedMemorySize, TG_TOTAL);
        cudaFuncSetAttribute(resfused<true,true>,  cudaFuncAttributeMaxDynamicSharedMemorySize, RF_TOTAL);
        cudaFuncSetAttribute(resfused<false,true>, cudaFuncAttributeMaxDynamicSharedMemorySize, RF_TOTAL);
    }

    const int TG_GRID = NROWS / 64;   // 512

    prep_w<<<112, 256>>>(wi, wj, rw1, rw2, wd, wfH, wfL);

    // xi = ssp(x)@wi.T+bi (fp32, exact hi/lo W) ; xjp = ssp(x)@wj.T+bj (fp16)
    tg2<0,true,false,false,true,false,false><<<TG_GRID, 256, TG_TOTAL>>>(
        x, wfH, wfL, bi, nullptr, nullptr, xi_p, nullptr);
    tg2<0,true,false,false,false,true,false><<<TG_GRID, 256, TG_TOTAL>>>(
        x, wfH + 16384, wfL + 16384, bj, nullptr, nullptr, nullptr, xjpH);

    // m0 = attention; emits fp16 ssp(m0) -> sf
    attn_mma<<<nsm, 512, SM_TOTAL>>>(rbf, idxj, k2f, xi_p, xjpH, m0_p, sf);

    // fused residual blocks (t never leaves smem)
    resfused<true,true><<<TG_GRID, 256, RF_TOTAL>>>(
        sf, wfH + 2*16384, wfH + 3*16384, rb1, rb2, m0_p, m1_p, sf);
    resfused<false,true><<<TG_GRID, 256, RF_TOTAL>>>(
        sf, wfH + 4*16384, wfH + 5*16384, rb1 + FDIM, rb2 + FDIM, m1_p, nullptr, sf);

    // out = u*x + ssp(m2)@wd+bd   (single-pass fp16 W)
    tg2<1,false,true,true,true,false,false><<<TG_GRID, 256, TG_TOTAL>>>(
        sf, wfH + 6*16384, nullptr, bd, x, u, out, nullptr);
}

// round 17
// speedup vs baseline: 1.9202x; 1.0825x over previous
#include <cuda_runtime.h>
#include <cuda_bf16.h>
#include <cuda_fp16.h>
#include <cstdint>
#include <math.h>

#define NROWS 32768
#define FDIM  128
#define KDIM  64
#define MNBR  32
#define NTILES (NROWS/4)

// Scratch (allocation-free rule: __device__ globals)
__device__ float g_xi [NROWS*FDIM];
__device__ float g_m0 [NROWS*FDIM];
__device__ float g_m1 [NROWS*FDIM];
__device__ __align__(16) __half g_xjpH[NROWS*FDIM];
__device__ __align__(16) __half g_wfH[7*16384];
__device__ __align__(16) __half g_wfL[7*16384];
__device__ __align__(16) __half g_sf[NROWS*FDIM];

__device__ __forceinline__ float sspf(float a) {
    return fmaxf(a, 0.0f) + log1pf(expf(-fabsf(a))) - 0.69314718055994530942f;
}

// ---------------- mma.sync / cp.async helpers ----------------
__device__ __forceinline__ uint32_t s2u(const void* p) {
    uint32_t a;
    asm("{ .reg .u64 t; cvta.to.shared.u64 t, %1; cvt.u32.u64 %0, t; }" : "=r"(a) : "l"(p));
    return a;
}

#define LDM_X4(r, addr) \
    asm volatile("ldmatrix.sync.aligned.m8n8.x4.shared.b16 {%0,%1,%2,%3}, [%4];" \
        : "=r"((r)[0]), "=r"((r)[1]), "=r"((r)[2]), "=r"((r)[3]) : "r"(addr))

#define MMA_F16(d, a, b0, b1) \
    asm volatile("mma.sync.aligned.m16n8k16.row.col.f32.f16.f16.f32 " \
        "{%0,%1,%2,%3}, {%4,%5,%6,%7}, {%8,%9}, {%0,%1,%2,%3};" \
        : "+f"((d)[0]), "+f"((d)[1]), "+f"((d)[2]), "+f"((d)[3]) \
        : "r"((a)[0]), "r"((a)[1]), "r"((a)[2]), "r"((a)[3]), "r"(b0), "r"(b1))

#define CP16(dst, src) \
    asm volatile("cp.async.cg.shared.global [%0], [%1], 16;" :: "r"(dst), "l"(src) : "memory")
#define CP_COMMIT() asm volatile("cp.async.commit_group;" ::: "memory")
#define CP_WAIT0()  asm volatile("cp.async.wait_group 0;" ::: "memory")

__device__ __forceinline__ void f16_split4(float4 v, __half* H, __half* L) {
    __half h0 = __float2half_rn(v.x), h1 = __float2half_rn(v.y),
           h2 = __float2half_rn(v.z), h3 = __float2half_rn(v.w);
    *(__half2*)(H)     = __half2(h0, h1);
    *(__half2*)(H + 2) = __half2(h2, h3);
    *(__half2*)(L)     = __half2(__float2half_rn(v.x - __half2float(h0)),
                                 __float2half_rn(v.y - __half2float(h1)));
    *(__half2*)(L + 2) = __half2(__float2half_rn(v.z - __half2float(h2)),
                                 __float2half_rn(v.w - __half2float(h3)));
}

// ---------------- weight pre-split ----------------
__global__ void __launch_bounds__(256) prep_w(
    const float* __restrict__ wi, const float* __restrict__ wj,
    const float* __restrict__ rw1, const float* __restrict__ rw2,
    const float* __restrict__ wd,
    __half* __restrict__ WH, __half* __restrict__ WL)
{
    int idx = blockIdx.x * 256 + threadIdx.x;
    int mat = idx >> 12, off = idx & 4095;
    const float* src;
    switch (mat) {
        case 0: src = wi; break;
        case 1: src = wj; break;
        case 2: src = rw1; break;
        case 3: src = rw2; break;
        case 4: src = rw1 + 16384; break;
        case 5: src = rw2 + 16384; break;
        default: src = wd; break;
    }
    float4 v = ((const float4*)src)[off];
    size_t d = (size_t)mat * 16384 + (size_t)off * 4;
    f16_split4(v, WH + d, WL + d);
}

// =================================================================================
// Fused x-GEMM: xi = ssp(x)@Wi+bi (fp32), xjp = ssp(x)@Wj+bj (fp16).
// Single-pass fp16 W for both. 256 threads, 64-row tile, 2 CTAs/SM.
// =================================================================================
#define XD_WI    0u               // 34816 (slab fp32 64x132 overlays after MMA1)
#define XD_WJ    34816u           // 34816
#define XD_A     69632u           // 17408
#define XD_BI    87040u
#define XD_BJ    87552u
#define XD_TOTAL 88064u
#define TG_SLABS 132

__global__ __launch_bounds__(256, 2) void xdual(
    const float* __restrict__ x,
    const __half* __restrict__ wiSrc, const __half* __restrict__ wjSrc,
    const float* __restrict__ bi, const float* __restrict__ bj,
    float* __restrict__ xiOut, __half* __restrict__ xjpOut)
{
    extern __shared__ char smem[];
    __half* AH = (__half*)(smem + XD_A);
    float* slab = (float*)(smem + XD_WI);   // overlays Wi after MMA1
    float* bis = (float*)(smem + XD_BI);
    float* bjs = (float*)(smem + XD_BJ);

    const int tid = threadIdx.x;
    const int wid = tid >> 5, lid = tid & 31;
    const uint32_t sb = s2u(smem);

    #pragma unroll
    for (int i = 0; i < 8; i++) {
        int idx = tid + 256 * i;
        int row = idx >> 4, c8 = idx & 15;
        *(uint4*)(smem + XD_WI + row * 272 + c8 * 16) = ((const uint4*)wiSrc)[idx];
        *(uint4*)(smem + XD_WJ + row * 272 + c8 * 16) = ((const uint4*)wjSrc)[idx];
    }
    if (tid < 128) {
        bis[tid] = bi[tid];
        bjs[tid] = bj[tid];
    }

    const int r0 = blockIdx.x * 64;

    // A = ssp(x) -> fp16
    #pragma unroll
    for (int i = 0; i < 8; i++) {
        int fidx = tid + 256 * i;
        float4 v = ((const float4*)(x + (size_t)r0 * FDIM))[fidx];
        v.x = sspf(v.x); v.y = sspf(v.y); v.z = sspf(v.z); v.w = sspf(v.w);
        int row = fidx >> 5, c = (fidx & 31) * 4;
        __half* dst = AH + row * 136 + c;
        *(__half2*)(dst)     = __floats2half2_rn(v.x, v.y);
        *(__half2*)(dst + 2) = __floats2half2_rn(v.z, v.w);
    }
    __syncthreads();

    const uint32_t aL_off = (((lid & 7) + (lid & 8)) * 136 + ((lid & 16) ? 8 : 0)) * 2;
    const uint32_t bL_off = (((lid & 7) + ((lid & 16) >> 1)) * 136 + ((lid & 8) ? 8 : 0)) * 2;
    const int wr = wid & 1, wc = wid >> 1;
    const int g = lid >> 2, t4 = lid & 3;

    float acc[2][4][4];

    // ---- pass 1: xi = A @ Wi ----
    #pragma unroll
    for (int mt = 0; mt < 2; mt++)
        #pragma unroll
        for (int nb = 0; nb < 4; nb++)
            #pragma unroll
            for (int c = 0; c < 4; c++) acc[mt][nb][c] = 0.f;

    #pragma unroll
    for (int kk = 0; kk < 8; kk++) {
        const uint32_t kb = (uint32_t)kk * 32;
        uint32_t ah[2][4], bh[2][4];
        #pragma unroll
        for (int mt = 0; mt < 2; mt++) {
            uint32_t ro = (uint32_t)(32*wr + 16*mt) * 272 + kb;
            LDM_X4(ah[mt], sb + XD_A + aL_off + ro);
        }
        #pragma unroll
        for (int np = 0; np < 2; np++) {
            uint32_t no = (uint32_t)(32*wc + 16*np) * 272 + kb;
            LDM_X4(bh[np], sb + XD_WI + bL_off + no);
        }
        #pragma unroll
        for (int mt = 0; mt < 2; mt++)
            #pragma unroll
            for (int np = 0; np < 2; np++) {
                MMA_F16(acc[mt][2*np],   ah[mt], bh[np][0], bh[np][1]);
                MMA_F16(acc[mt][2*np+1], ah[mt], bh[np][2], bh[np][3]);
            }
    }
    __syncthreads();   // Wi reads done -> slab overlays

    #pragma unroll
    for (int mt = 0; mt < 2; mt++)
        #pragma unroll
        for (int nb = 0; nb < 4; nb++) {
            int e = 32*wr + 16*mt + g;
            int c = 32*wc + 8*nb + 2*t4;
            *(float2*)&slab[e * TG_SLABS + c] = make_float2(acc[mt][nb][0], acc[mt][nb][1]);
            *(float2*)&slab[(e+8) * TG_SLABS + c] = make_float2(acc[mt][nb][2], acc[mt][nb][3]);
        }
    __syncthreads();

    #pragma unroll
    for (int i = 0; i < 32; i++) {
        int idx = tid + 256 * i;
        int row = idx >> 7, col = idx & 127;
        xiOut[(size_t)(r0 + row) * FDIM + col] = slab[row * TG_SLABS + col] + bis[col];
    }
    __syncthreads();   // slab reads done

    // ---- pass 2: xjp = A @ Wj ----
    #pragma unroll
    for (int mt = 0; mt < 2; mt++)
        #pragma unroll
        for (int nb = 0; nb < 4; nb++)
            #pragma unroll
            for (int c = 0; c < 4; c++) acc[mt][nb][c] = 0.f;

    #pragma unroll
    for (int kk = 0; kk < 8; kk++) {
        const uint32_t kb = (uint32_t)kk * 32;
        uint32_t ah[2][4], bh[2][4];
        #pragma unroll
        for (int mt = 0; mt < 2; mt++) {
            uint32_t ro = (uint32_t)(32*wr + 16*mt) * 272 + kb;
            LDM_X4(ah[mt], sb + XD_A + aL_off + ro);
        }
        #pragma unroll
        for (int np = 0; np < 2; np++) {
            uint32_t no = (uint32_t)(32*wc + 16*np) * 272 + kb;
            LDM_X4(bh[np], sb + XD_WJ + bL_off + no);
        }
        #pragma unroll
        for (int mt = 0; mt < 2; mt++)
            #pragma unroll
            for (int np = 0; np < 2; np++) {
                MMA_F16(acc[mt][2*np],   ah[mt], bh[np][0], bh[np][1]);
                MMA_F16(acc[mt][2*np+1], ah[mt], bh[np][2], bh[np][3]);
            }
    }
    __syncthreads();

    #pragma unroll
    for (int mt = 0; mt < 2; mt++)
        #pragma unroll
        for (int nb = 0; nb < 4; nb++) {
            int e = 32*wr + 16*mt + g;
            int c = 32*wc + 8*nb + 2*t4;
            *(float2*)&slab[e * TG_SLABS + c] = make_float2(acc[mt][nb][0], acc[mt][nb][1]);
            *(float2*)&slab[(e+8) * TG_SLABS + c] = make_float2(acc[mt][nb][2], acc[mt][nb][3]);
        }
    __syncthreads();

    #pragma unroll
    for (int i = 0; i < 32; i++) {
        int idx = tid + 256 * i;
        int row = idx >> 7, col = idx & 127;
        xjpOut[(size_t)(r0 + row) * FDIM + col] =
            __float2half_rn(slab[row * TG_SLABS + col] + bjs[col]);
    }
}

// =================================================================================
// Tensor-core row GEMM (validated R15) — used for the final output GEMM
// =================================================================================
#define TG_WH    0u
#define TG_WL    34816u
#define TG_U     69632u
#define TG_AH    TG_U
#define TG_BIAS  103424u
#define TG_MUL   103936u
#define TG_TOTAL 104448u

template<int AMODE, bool W2P, bool ADD, bool MULVEC, bool OUTF32, bool OUTSPLIT, bool OSSP>
__global__ __launch_bounds__(256, 2) void tg2(
    const void* __restrict__ aSrc,
    const __half* __restrict__ wHsrc, const __half* __restrict__ wLsrc,
    const float* __restrict__ bias, const float* __restrict__ addp,
    const float* __restrict__ mulv, float* __restrict__ outf,
    __half* __restrict__ oH)
{
    extern __shared__ char smem[];
    __half* AH = (__half*)(smem + TG_AH);
    float* slab = (float*)(smem + TG_U);
    float* b_sm = (float*)(smem + TG_BIAS);
    float* u_sm = (float*)(smem + TG_MUL);

    const int tid = threadIdx.x;
    const int wid = tid >> 5, lid = tid & 31;
    const uint32_t sb = s2u(smem);

    #pragma unroll
    for (int i = 0; i < 8; i++) {
        int idx = tid + 256 * i;
        int row = idx >> 4, c8 = idx & 15;
        *(uint4*)(smem + TG_WH + row * 272 + c8 * 16) = ((const uint4*)wHsrc)[idx];
        if (W2P)
            *(uint4*)(smem + TG_WL + row * 272 + c8 * 16) = ((const uint4*)wLsrc)[idx];
    }
    if (tid < 128) {
        b_sm[tid] = bias[tid];
        u_sm[tid] = MULVEC ? mulv[tid] : 0.0f;
    }

    const int r0 = blockIdx.x * 64;

    if (AMODE == 0) {
        #pragma unroll
        for (int i = 0; i < 8; i++) {
            int fidx = tid + 256 * i;
            float4 v = ((const float4*)((const float*)aSrc + (size_t)r0 * FDIM))[fidx];
            v.x = sspf(v.x); v.y = sspf(v.y); v.z = sspf(v.z); v.w = sspf(v.w);
            int row = fidx >> 5, c = (fidx & 31) * 4;
            __half* dst = AH + row * 136 + c;
            *(__half2*)(dst)     = __floats2half2_rn(v.x, v.y);
            *(__half2*)(dst + 2) = __floats2half2_rn(v.z, v.w);
        }
    } else {
        const uint4* a4 = (const uint4*)((const __half*)aSrc + (size_t)r0 * FDIM);
        #pragma unroll
        for (int i = 0; i < 4; i++) {
            int idx = tid + 256 * i;
            int row = idx >> 4, c8 = idx & 15;
            *(uint4*)(smem + TG_AH + row * 272 + c8 * 16) = a4[idx];
        }
    }
    __syncthreads();

    const uint32_t aL_off = (((lid & 7) + (lid & 8)) * 136 + ((lid & 16) ? 8 : 0)) * 2;
    const uint32_t bL_off = (((lid & 7) + ((lid & 16) >> 1)) * 136 + ((lid & 8) ? 8 : 0)) * 2;
    const int wr = wid & 1, wc = wid >> 1;

    float acc[2][4][4];
    #pragma unroll
    for (int mt = 0; mt < 2; mt++)
        #pragma unroll
        for (int nb = 0; nb < 4; nb++)
            #pragma unroll
            for (int c = 0; c < 4; c++) acc[mt][nb][c] = 0.f;

    #pragma unroll
    for (int kk = 0; kk < 8; kk++) {
        const uint32_t kb = (uint32_t)kk * 32;
        uint32_t ah[2][4], bh[2][4], bl[2][4];
        #pragma unroll
        for (int mt = 0; mt < 2; mt++) {
            uint32_t ro = (uint32_t)(32*wr + 16*mt) * 272 + kb;
            LDM_X4(ah[mt], sb + TG_AH + aL_off + ro);
        }
        #pragma unroll
        for (int np = 0; np < 2; np++) {
            uint32_t no = (uint32_t)(32*wc + 16*np) * 272 + kb;
            LDM_X4(bh[np], sb + TG_WH + bL_off + no);
            if (W2P) LDM_X4(bl[np], sb + TG_WL + bL_off + no);
        }
        #pragma unroll
        for (int mt = 0; mt < 2; mt++)
            #pragma unroll
            for (int np = 0; np < 2; np++) {
                MMA_F16(acc[mt][2*np],   ah[mt], bh[np][0], bh[np][1]);
                MMA_F16(acc[mt][2*np+1], ah[mt], bh[np][2], bh[np][3]);
                if (W2P) {
                    MMA_F16(acc[mt][2*np],   ah[mt], bl[np][0], bl[np][1]);
                    MMA_F16(acc[mt][2*np+1], ah[mt], bl[np][2], bl[np][3]);
                }
            }
    }
    __syncthreads();

    {
        const int g = lid >> 2, t = lid & 3;
        #pragma unroll
        for (int mt = 0; mt < 2; mt++)
            #pragma unroll
            for (int nb = 0; nb < 4; nb++) {
                int e = 32*wr + 16*mt + g;
                int c = 32*wc + 8*nb + 2*t;
                *(float2*)&slab[e * TG_SLABS + c] = make_float2(acc[mt][nb][0], acc[mt][nb][1]);
                *(float2*)&slab[(e+8) * TG_SLABS + c] = make_float2(acc[mt][nb][2], acc[mt][nb][3]);
            }
    }
    __syncthreads();

    #pragma unroll
    for (int i = 0; i < 32; i++) {
        int idx = tid + 256 * i;
        int row = idx >> 7, col = idx & 127;
        size_t gpos = (size_t)(r0 + row) * FDIM + col;
        float o = slab[row * TG_SLABS + col] + b_sm[col];
        if (ADD) {
            float av = addp[gpos];
            o += MULVEC ? av * u_sm[col] : av;
        }
        if (OUTF32) outf[gpos] = o;
        if (OUTSPLIT) {
            float s = OSSP ? sspf(o) : o;
            oH[gpos] = __float2half_rn(s);
        }
    }
}

// =================================================================================
// Fused residual block (validated R15)
// =================================================================================
#define RF_W1    0u
#define RF_W2    34816u
#define RF_A     69632u
#define RF_T     87040u
#define RF_SLAB  RF_A
#define RF_B1    104448u
#define RF_B2    104960u
#define RF_TOTAL 105472u

template<bool OUTF32, bool OUTSPLIT>
__global__ __launch_bounds__(256, 2) void resfused(
    const __half* __restrict__ aSrc,
    const __half* __restrict__ w1src, const __half* __restrict__ w2src,
    const float* __restrict__ b1, const float* __restrict__ b2,
    const float* __restrict__ addp, float* __restrict__ outf,
    __half* __restrict__ oH)
{
    extern __shared__ char smem[];
    __half* Th = (__half*)(smem + RF_T);
    float* slab = (float*)(smem + RF_SLAB);
    float* b1s = (float*)(smem + RF_B1);
    float* b2s = (float*)(smem + RF_B2);

    const int tid = threadIdx.x;
    const int wid = tid >> 5, lid = tid & 31;
    const uint32_t sb = s2u(smem);

    #pragma unroll
    for (int i = 0; i < 8; i++) {
        int idx = tid + 256 * i;
        int row = idx >> 4, c8 = idx & 15;
        *(uint4*)(smem + RF_W1 + row * 272 + c8 * 16) = ((const uint4*)w1src)[idx];
        *(uint4*)(smem + RF_W2 + row * 272 + c8 * 16) = ((const uint4*)w2src)[idx];
    }
    if (tid < 128) {
        b1s[tid] = b1[tid];
        b2s[tid] = b2[tid];
    }

    const int r0 = blockIdx.x * 64;

    {
        const uint4* a4 = (const uint4*)(aSrc + (size_t)r0 * FDIM);
        #pragma unroll
        for (int i = 0; i < 4; i++) {
            int idx = tid + 256 * i;
            int row = idx >> 4, c8 = idx & 15;
            *(uint4*)(smem + RF_A + row * 272 + c8 * 16) = a4[idx];
        }
    }
    __syncthreads();

    const uint32_t aL_off = (((lid & 7) + (lid & 8)) * 136 + ((lid & 16) ? 8 : 0)) * 2;
    const uint32_t bL_off = (((lid & 7) + ((lid & 16) >> 1)) * 136 + ((lid & 8) ? 8 : 0)) * 2;
    const int wr = wid & 1, wc = wid >> 1;
    const int g = lid >> 2, t4 = lid & 3;

    float acc[2][4][4];

    #pragma unroll
    for (int mt = 0; mt < 2; mt++)
        #pragma unroll
        for (int nb = 0; nb < 4; nb++)
            #pragma unroll
            for (int c = 0; c < 4; c++) acc[mt][nb][c] = 0.f;

    #pragma unroll
    for (int kk = 0; kk < 8; kk++) {
        const uint32_t kb = (uint32_t)kk * 32;
        uint32_t ah[2][4], bh[2][4];
        #pragma unroll
        for (int mt = 0; mt < 2; mt++) {
            uint32_t ro = (uint32_t)(32*wr + 16*mt) * 272 + kb;
            LDM_X4(ah[mt], sb + RF_A + aL_off + ro);
        }
        #pragma unroll
        for (int np = 0; np < 2; np++) {
            uint32_t no = (uint32_t)(32*wc + 16*np) * 272 + kb;
            LDM_X4(bh[np], sb + RF_W1 + bL_off + no);
        }
        #pragma unroll
        for (int mt = 0; mt < 2; mt++)
            #pragma unroll
            for (int np = 0; np < 2; np++) {
                MMA_F16(acc[mt][2*np],   ah[mt], bh[np][0], bh[np][1]);
                MMA_F16(acc[mt][2*np+1], ah[mt], bh[np][2], bh[np][3]);
            }
    }

    #pragma unroll
    for (int mt = 0; mt < 2; mt++)
        #pragma unroll
        for (int nb = 0; nb < 4; nb++) {
            int e = 32*wr + 16*mt + g;
            int c = 32*wc + 8*nb + 2*t4;
            float bb0 = b1s[c], bb1 = b1s[c+1];
            *(__half2*)&Th[e * 136 + c] =
                __floats2half2_rn(acc[mt][nb][0] + bb0, acc[mt][nb][1] + bb1);
            *(__half2*)&Th[(e+8) * 136 + c] =
                __floats2half2_rn(acc[mt][nb][2] + bb0, acc[mt][nb][3] + bb1);
        }
    __syncthreads();

    #pragma unroll
    for (int mt = 0; mt < 2; mt++)
        #pragma unroll
        for (int nb = 0; nb < 4; nb++)
            #pragma unroll
            for (int c = 0; c < 4; c++) acc[mt][nb][c] = 0.f;

    #pragma unroll
    for (int kk = 0; kk < 8; kk++) {
        const uint32_t kb = (uint32_t)kk * 32;
        uint32_t ah[2][4], bh[2][4];
        #pragma unroll
        for (int mt = 0; mt < 2; mt++) {
            uint32_t ro = (uint32_t)(32*wr + 16*mt) * 272 + kb;
            LDM_X4(ah[mt], sb + RF_T + aL_off + ro);
        }
        #pragma unroll
        for (int np = 0; np < 2; np++) {
            uint32_t no = (uint32_t)(32*wc + 16*np) * 272 + kb;
            LDM_X4(bh[np], sb + RF_W2 + bL_off + no);
        }
        #pragma unroll
        for (int mt = 0; mt < 2; mt++)
            #pragma unroll
            for (int np = 0; np < 2; np++) {
                MMA_F16(acc[mt][2*np],   ah[mt], bh[np][0], bh[np][1]);
                MMA_F16(acc[mt][2*np+1], ah[mt], bh[np][2], bh[np][3]);
            }
    }
    __syncthreads();

    #pragma unroll
    for (int mt = 0; mt < 2; mt++)
        #pragma unroll
        for (int nb = 0; nb < 4; nb++) {
            int e = 32*wr + 16*mt + g;
            int c = 32*wc + 8*nb + 2*t4;
            *(float2*)&slab[e * TG_SLABS + c] = make_float2(acc[mt][nb][0], acc[mt][nb][1]);
            *(float2*)&slab[(e+8) * TG_SLABS + c] = make_float2(acc[mt][nb][2], acc[mt][nb][3]);
        }
    __syncthreads();

    #pragma unroll
    for (int i = 0; i < 32; i++) {
        int idx = tid + 256 * i;
        int row = idx >> 7, col = idx & 127;
        size_t gpos = (size_t)(r0 + row) * FDIM + col;
        float o = slab[row * TG_SLABS + col] + b2s[col] + addp[gpos];
        if (OUTF32) outf[gpos] = o;
        if (OUTSPLIT) oH[gpos] = __float2half_rn(sspf(o));
    }
}

// =================================================================================
// Fused edge-filter GEMM + gather + attention (validated R16, gather moved earlier)
// =================================================================================
#define OFF_BH    0u
#define OFF_U     18432u
#define OFF_AH    OFF_U
#define OFF_XPB   53248u
#define OFF_STG   86016u
#define OFF_XI2   118784u
#define OFF_PARTL 122880u
#define OFF_PARTP 139776u
#define OFF_ATT   156160u
#define OFF_JB    156672u
#define SM_TOTAL  157696u
#define SLAB_H    136

__global__ void __launch_bounds__(512, 1) attn_mma(
    const float* __restrict__ rbf, const int* __restrict__ idxj,
    const float* __restrict__ k2f, const float* __restrict__ xi,
    const __half* __restrict__ xjph, float* __restrict__ mout,
    __half* __restrict__ oH)
{
    extern __shared__ char smem[];
    __half* AH = (__half*)(smem + OFF_AH);
    __half* BH = (__half*)(smem + OFF_BH);
    __half* slabh = (__half*)(smem + OFF_U);
    __half* xpbh  = (__half*)(smem + OFF_XPB);
    float* partL  = (float*)(smem + OFF_PARTL);
    float* partP  = (float*)(smem + OFF_PARTP);
    float* att_sm = (float*)(smem + OFF_ATT);

    const int tid = threadIdx.x;
    const int wid = tid >> 5, lid = tid & 31;
    const uint32_t sb = s2u(smem);

    #pragma unroll
    for (int i = 0; i < 4; i++) {
        int fidx = tid + 512 * i;
        float4 v = ((const float4*)k2f)[fidx];
        int row = fidx >> 4, c = (fidx & 15) * 4;
        __half* dst = BH + row*72 + c;
        *(__half2*)(dst)     = __floats2half2_rn(v.x, v.y);
        *(__half2*)(dst + 2) = __floats2half2_rn(v.z, v.w);
    }

    const uint32_t aL = ((((lid & 7) + (lid & 8)) * 72) + ((lid & 16) ? 8 : 0)) * 2;
    const uint32_t bL = ((((lid & 7) + ((lid & 16) >> 1)) * 72) + ((lid & 8) ? 8 : 0)) * 2;
    const int wr = wid & 3, wc = wid >> 2;
    const int e0  = tid >> 6;
    const int cpi = tid & 63;
    const int c0  = cpi * 2;
    const int q   = cpi >> 4;
    const int mmE = (cpi & 15) * 2;
    const int ctb = e0 * 4 + q;
    const int stride = gridDim.x;

    auto stage = [&](int tile, int sel) {
        const char* rsrc = (const char*)(rbf + (size_t)tile * 8192);
        #pragma unroll
        for (int i = 0; i < 4; i++) {
            uint32_t o = (uint32_t)(tid + 512 * i) * 16u;
            CP16(sb + OFF_STG + o, rsrc + o);
        }
        if (tid < 128)
            CP16(sb + OFF_XI2 + (uint32_t)sel * 2048u + tid * 16u,
                 (const char*)(xi + (size_t)tile * 512) + tid * 16);
        if (tid < 32)
            CP16(sb + OFF_JB + (uint32_t)sel * 512u + tid * 16u,
                 (const char*)(idxj + tile * 128) + tid * 16);
    };
    auto gather = [&](int sel) {
        const int* jb = (const int*)(smem + OFF_JB + sel * 512);
        const int half_sel = lid >> 4;
        const uint32_t lane_off = (uint32_t)(lid & 15) * 16u;
        #pragma unroll
        for (int r = 0; r < 4; r++) {
            int e = wid * 8 + r * 2 + half_sel;
            int j = jb[e];
            CP16(sb + OFF_XPB + (uint32_t)e * 256u + lane_off,
                 (const char*)(xjph + (size_t)j * FDIM) + lane_off);
        }
    };

    int cur = 0;
    stage(blockIdx.x, 0);
    CP_COMMIT();
    CP_WAIT0();
    __syncthreads();
    gather(0);
    CP_COMMIT();

    for (int tile = blockIdx.x; tile < NTILES; tile += stride) {
        const int n0 = tile * 4;
        const int nxt = tile + stride;
        const bool has = nxt < NTILES;

        #pragma unroll
        for (int i = 0; i < 4; i++) {
            int fidx = tid + 512 * i;
            float4 v = *(const float4*)(smem + OFF_STG + (uint32_t)fidx * 16u);
            int row = fidx >> 4, c = (fidx & 15) * 4;
            __half* dst = AH + row*72 + c;
            *(__half2*)(dst)     = __floats2half2_rn(v.x, v.y);
            *(__half2*)(dst + 2) = __floats2half2_rn(v.z, v.w);
        }
        if (has) stage(nxt, cur ^ 1);
        CP_COMMIT();
        __syncthreads();

        float acc[2][4][4];
        #pragma unroll
        for (int mt = 0; mt < 2; mt++)
            #pragma unroll
            for (int nb = 0; nb < 4; nb++)
                #pragma unroll
                for (int c = 0; c < 4; c++) acc[mt][nb][c] = 0.f;

        #pragma unroll
        for (int kk = 0; kk < 4; kk++) {
            const uint32_t kb = (uint32_t)kk * 32;
            uint32_t ah[2][4], bh[2][4];
            #pragma unroll
            for (int mt = 0; mt < 2; mt++) {
                uint32_t ro = (uint32_t)(32*wr + 16*mt) * 144 + kb;
                LDM_X4(ah[mt], sb + OFF_AH + aL + ro);
            }
            #pragma unroll
            for (int np = 0; np < 2; np++) {
                uint32_t no = (uint32_t)(32*wc + 16*np) * 144 + kb;
                LDM_X4(bh[np], sb + OFF_BH + bL + no);
            }
            #pragma unroll
            for (int mt = 0; mt < 2; mt++)
                #pragma unroll
                for (int np = 0; np < 2; np++) {
                    MMA_F16(acc[mt][2*np],   ah[mt], bh[np][0], bh[np][1]);
                    MMA_F16(acc[mt][2*np+1], ah[mt], bh[np][2], bh[np][3]);
                }
        }
        __syncthreads();

        {
            const int g = lid >> 2, t = lid & 3;
            #pragma unroll
            for (int mt = 0; mt < 2; mt++)
                #pragma unroll
                for (int nb = 0; nb < 4; nb++) {
                    int e = 32*wr + 16*mt + g;
                    int c = 32*wc + 8*nb + 2*t;
                    *(__half2*)&slabh[e * SLAB_H + c] =
                        __floats2half2_rn(acc[mt][nb][0], acc[mt][nb][1]);
                    *(__half2*)&slabh[(e + 8) * SLAB_H + c] =
                        __floats2half2_rn(acc[mt][nb][2], acc[mt][nb][3]);
                }
        }
        CP_WAIT0();
        __syncthreads();

        const float* xi_c = (const float*)(smem + OFF_XI2 + (uint32_t)cur * 2048u);

        __half2 xp2[16];
        float lE[4] = {0.f, 0.f, 0.f, 0.f};
        float lO[4] = {0.f, 0.f, 0.f, 0.f};
        #pragma unroll
        for (int i = 0; i < 16; i++) {
            const int e = 8*i + e0;
            const int a = i >> 2;
            const int m = e & 31;
            __half2 s2 = *(const __half2*)&slabh[e * SLAB_H + c0];
            __half2 x2 = *(const __half2*)&xpbh[e * 128 + c0];
            __half2 p2 = __hmul2(s2, x2);
            xp2[i] = p2;
            float2 pf = __half22float2(p2);
            float w = xi_c[a * FDIM + 4*m + q];
            lE[a] += w * pf.x;
            lO[a] += w * pf.y;
        }
        #pragma unroll
        for (int a = 0; a < 4; a++) {
            partL[(a*32 + mmE)     * 33 + ctb] = lE[a];
            partL[(a*32 + mmE + 1) * 33 + ctb] = lO[a];
        }
        // xpb fully consumed -> prefetch next tile's gather now (extra overlap window)
        if (has) gather(cur ^ 1);
        CP_COMMIT();
        __syncthreads();

        if (tid < 128) {
            float lg = 0.f;
            #pragma unroll
            for (int c2 = 0; c2 < 32; c2++) lg += partL[tid * 33 + c2];
            float mx = lg;
            #pragma unroll
            for (int o = 16; o; o >>= 1) mx = fmaxf(mx, __shfl_xor_sync(0xffffffffu, mx, o));
            float ex = expf(lg - mx);
            float smv = ex;
            #pragma unroll
            for (int o = 16; o; o >>= 1) smv += __shfl_xor_sync(0xffffffffu, smv, o);
            att_sm[tid] = ex / smv;
        }
        __syncthreads();

        float pE[4] = {0.f, 0.f, 0.f, 0.f};
        float pO[4] = {0.f, 0.f, 0.f, 0.f};
        #pragma unroll
        for (int i = 0; i < 16; i++) {
            const int e = 8*i + e0;
            const int a = i >> 2;
            const int m = e & 31;
            float w = att_sm[a * 32 + m];
            float2 pf = __half22float2(xp2[i]);
            pE[a] += w * pf.x;
            pO[a] += w * pf.y;
        }
        #pragma unroll
        for (int a = 0; a < 4; a++)
            *(float2*)&partP[e0 * 512 + a * 128 + c0] = make_float2(pE[a], pO[a]);
        __syncthreads();

        {
            size_t gpos = (size_t)n0 * FDIM + tid;
            float mv = xi_c[tid];
            #pragma unroll
            for (int g2 = 0; g2 < 8; g2++) mv += partP[g2 * 512 + tid];
            mout[gpos] = mv;
            oH[gpos] = __float2half_rn(sspf(mv));
        }
        __syncthreads();
        cur ^= 1;
    }
}

extern "C" void kernel_launch(void* const* d_in, const int* in_sizes, int n_in,
                              void* d_out, int out_size)
{
    const float* x    = (const float*)d_in[0];
    const float* rbf  = (const float*)d_in[1];
    const int*   idxj = (const int*)  d_in[3];
    const float* k2f  = (const float*)d_in[4];
    const float* wi   = (const float*)d_in[5];
    const float* bi   = (const float*)d_in[6];
    const float* wj   = (const float*)d_in[7];
    const float* bj   = (const float*)d_in[8];
    const float* rw1  = (const float*)d_in[9];
    const float* rb1  = (const float*)d_in[10];
    const float* rw2  = (const float*)d_in[11];
    const float* rb2  = (const float*)d_in[12];
    const float* wd   = (const float*)d_in[13];
    const float* bd   = (const float*)d_in[14];
    const float* u    = (const float*)d_in[15];
    float* out = (float*)d_out;

    float *xi_p, *m0_p, *m1_p;
    __half *xjpH, *wfH, *wfL, *sf;
    cudaGetSymbolAddress((void**)&xi_p,  g_xi);
    cudaGetSymbolAddress((void**)&m0_p,  g_m0);
    cudaGetSymbolAddress((void**)&m1_p,  g_m1);
    cudaGetSymbolAddress((void**)&xjpH,  g_xjpH);
    cudaGetSymbolAddress((void**)&wfH,   g_wfH);
    cudaGetSymbolAddress((void**)&wfL,   g_wfL);
    cudaGetSymbolAddress((void**)&sf,    g_sf);

    static int nsm = 0;
    if (nsm == 0) {
        cudaDeviceGetAttribute(&nsm, cudaDevAttrMultiProcessorCount, 0);
        if (nsm <= 0) nsm = 148;
        cudaFuncSetAttribute(attn_mma, cudaFuncAttributeMaxDynamicSharedMemorySize, SM_TOTAL);
        cudaFuncSetAttribute(xdual, cudaFuncAttributeMaxDynamicSharedMemorySize, XD_TOTAL);
        cudaFuncSetAttribute(tg2<1,false,true,true,true,false,false>,   cudaFuncAttributeMaxDynamicSharedMemorySize, TG_TOTAL);
        cudaFuncSetAttribute(resfused<true,true>,  cudaFuncAttributeMaxDynamicSharedMemorySize, RF_TOTAL);
        cudaFuncSetAttribute(resfused<false,true>, cudaFuncAttributeMaxDynamicSharedMemorySize, RF_TOTAL);
    }

    const int TG_GRID = NROWS / 64;   // 512

    prep_w<<<112, 256>>>(wi, wj, rw1, rw2, wd, wfH, wfL);

    // fused: xi = ssp(x)@wi+bi (fp32), xjp = ssp(x)@wj+bj (fp16)
    xdual<<<TG_GRID, 256, XD_TOTAL>>>(x, wfH, wfH + 16384, bi, bj, xi_p, xjpH);

    // m0 = attention; emits fp16 ssp(m0) -> sf
    attn_mma<<<nsm, 512, SM_TOTAL>>>(rbf, idxj, k2f, xi_p, xjpH, m0_p, sf);

    // fused residual blocks
    resfused<true,true><<<TG_GRID, 256, RF_TOTAL>>>(
        sf, wfH + 2*16384, wfH + 3*16384, rb1, rb2, m0_p, m1_p, sf);
    resfused<false,true><<<TG_GRID, 256, RF_TOTAL>>>(
        sf, wfH + 4*16384, wfH + 5*16384, rb1 + FDIM, rb2 + FDIM, m1_p, nullptr, sf);

    // out = u*x + ssp(m2)@wd+bd
    tg2<1,false,true,true,true,false,false><<<TG_GRID, 256, TG_TOTAL>>>(
        sf, wfH + 6*16384, nullptr, bd, x, u, out, nullptr);
}